// round 2
// baseline (speedup 1.0000x reference)
#include <cuda_runtime.h>
#include <cstddef>

#define EDIM   768
#define BATCH  8
#define SEQ    1024
#define NH     12
#define HD     64
#define MTOT   (BATCH * SEQ)   // 8192

// Scratch (no cudaMalloc allowed): Q, K projections and attention output.
__device__ float g_Q[(size_t)MTOT * EDIM];
__device__ float g_K[(size_t)MTOT * EDIM];
__device__ float g_O[(size_t)MTOT * EDIM];

// ---------------------------------------------------------------------------
// GEMM (NT): C[m][n] = sum_k A[m][k] * W[n][k] + bias[n]
// A: [M,K] row-major, W: [N,K] row-major. BM=BN=64, BK=16, 256 threads, 4x4.
// ---------------------------------------------------------------------------
#define BM 64
#define BN 64
#define BK 16
#define GP 68   // smem pitch (floats): multiple of 4 for LDS.128, not mult of 64

__global__ __launch_bounds__(256) void gemm_nt_bias(
    const float* __restrict__ A, const float* __restrict__ W,
    const float* __restrict__ bias, float* __restrict__ C,
    int M, int N, int K)
{
    __shared__ float As[BK][GP];  // As[k][m]
    __shared__ float Ws[BK][GP];  // Ws[k][n]

    const int tid = threadIdx.x;
    const int tx = tid & 15;
    const int ty = tid >> 4;
    const int m0 = blockIdx.y * BM;
    const int n0 = blockIdx.x * BN;

    const int r  = tid >> 2;          // 0..63
    const int c4 = (tid & 3) << 2;    // 0,4,8,12  (covers BK=16)

    const float* Ap = A + (size_t)(m0 + r) * K + c4;
    const float* Wp = W + (size_t)(n0 + r) * K + c4;

    float acc[4][4] = {};

    for (int k0 = 0; k0 < K; k0 += BK) {
        float4 av = *reinterpret_cast<const float4*>(Ap + k0);
        float4 wv = *reinterpret_cast<const float4*>(Wp + k0);
        __syncthreads();
        As[c4 + 0][r] = av.x; As[c4 + 1][r] = av.y;
        As[c4 + 2][r] = av.z; As[c4 + 3][r] = av.w;
        Ws[c4 + 0][r] = wv.x; Ws[c4 + 1][r] = wv.y;
        Ws[c4 + 2][r] = wv.z; Ws[c4 + 3][r] = wv.w;
        __syncthreads();

#pragma unroll
        for (int k = 0; k < BK; k++) {
            float4 a = *reinterpret_cast<const float4*>(&As[k][ty * 4]);
            float4 b = *reinterpret_cast<const float4*>(&Ws[k][tx * 4]);
            float aa[4] = {a.x, a.y, a.z, a.w};
            float bb[4] = {b.x, b.y, b.z, b.w};
#pragma unroll
            for (int i = 0; i < 4; i++)
#pragma unroll
                for (int j = 0; j < 4; j++)
                    acc[i][j] = fmaf(aa[i], bb[j], acc[i][j]);
        }
    }

#pragma unroll
    for (int i = 0; i < 4; i++) {
        const int m = m0 + ty * 4 + i;
#pragma unroll
        for (int j = 0; j < 4; j++) {
            const int n = n0 + tx * 4 + j;
            C[(size_t)m * N + n] = acc[i][j] + bias[n];
        }
    }
}

// ---------------------------------------------------------------------------
// Flash attention: one CTA per (qtile=64 rows, head, batch). V == K.
// smem: Qst[d][row] (scaled), Kst[d][key], Kn[key][d], Pst[key][row]
// ---------------------------------------------------------------------------
#define AP 68
#define ATTN_SMEM_FLOATS (4 * 64 * AP)
#define ATTN_SMEM_BYTES  (ATTN_SMEM_FLOATS * 4)

__global__ __launch_bounds__(256) void attn_kernel(
    const float* __restrict__ Q, const float* __restrict__ K,
    float* __restrict__ O)
{
    extern __shared__ float sm[];
    float* Qst = sm;                 // [HD][AP]  Qst[d*AP + row]
    float* Kst = Qst + HD * AP;      // [HD][AP]  Kst[d*AP + key]
    float* Kn  = Kst + HD * AP;      // [64][AP]  Kn[key*AP + d]
    float* Pst = Kn  + 64 * AP;      // [64][AP]  Pst[key*AP + row]

    const int tid = threadIdx.x;
    const int tx = tid & 15;
    const int ty = tid >> 4;
    const int qt = blockIdx.x;   // 0..15
    const int h  = blockIdx.y;   // 0..11
    const int b  = blockIdx.z;   // 0..7
    const float scale = 0.125f;  // 1/sqrt(64)

    const int r  = tid >> 2;          // 0..63 : row/key within tile
    const int d0 = (tid & 3) << 4;    // 0,16,32,48 : base of this thread's d-chunk
    const int q0 = qt * 64;

    // Load Q tile (pre-scaled) into d-major layout. Each thread covers
    // 16 consecutive dims (4 float4s) of its row -> full 64 dims per row.
    {
        const float* qrow = &Q[((size_t)(b * SEQ + q0 + r)) * EDIM + h * HD];
#pragma unroll
        for (int c = 0; c < 4; c++) {
            const int d4 = d0 + c * 4;
            float4 qv = *reinterpret_cast<const float4*>(qrow + d4);
            Qst[(d4 + 0) * AP + r] = qv.x * scale;
            Qst[(d4 + 1) * AP + r] = qv.y * scale;
            Qst[(d4 + 2) * AP + r] = qv.z * scale;
            Qst[(d4 + 3) * AP + r] = qv.w * scale;
        }
    }

    float o[4][4] = {};
    float mrow[4], lrow[4];
#pragma unroll
    for (int i = 0; i < 4; i++) { mrow[i] = -1e30f; lrow[i] = 0.0f; }

    for (int kt = 0; kt < SEQ / 64; kt++) {
        __syncthreads();  // previous PV done with Kn/Pst; Q write visible (iter 0)
        // Load K tile into both layouts (full 64 dims per key row).
        {
            const float* krow = &K[((size_t)(b * SEQ + kt * 64 + r)) * EDIM + h * HD];
#pragma unroll
            for (int c = 0; c < 4; c++) {
                const int d4 = d0 + c * 4;
                float4 kv = *reinterpret_cast<const float4*>(krow + d4);
                *reinterpret_cast<float4*>(&Kn[r * AP + d4]) = kv;
                Kst[(d4 + 0) * AP + r] = kv.x;
                Kst[(d4 + 1) * AP + r] = kv.y;
                Kst[(d4 + 2) * AP + r] = kv.z;
                Kst[(d4 + 3) * AP + r] = kv.w;
            }
        }
        __syncthreads();

        // S = (Q*scale) K^T : rows ty*4+i (query), cols tx*4+j (key)
        float s[4][4] = {};
#pragma unroll 16
        for (int d = 0; d < HD; d++) {
            float4 a = *reinterpret_cast<const float4*>(&Qst[d * AP + ty * 4]);
            float4 v = *reinterpret_cast<const float4*>(&Kst[d * AP + tx * 4]);
            float aa[4] = {a.x, a.y, a.z, a.w};
            float bb[4] = {v.x, v.y, v.z, v.w};
#pragma unroll
            for (int i = 0; i < 4; i++)
#pragma unroll
                for (int j = 0; j < 4; j++)
                    s[i][j] = fmaf(aa[i], bb[j], s[i][j]);
        }

        // Online softmax update per query row (16 tx-lanes hold a row).
#pragma unroll
        for (int i = 0; i < 4; i++) {
            float rmax = fmaxf(fmaxf(s[i][0], s[i][1]), fmaxf(s[i][2], s[i][3]));
#pragma unroll
            for (int off = 8; off > 0; off >>= 1)
                rmax = fmaxf(rmax, __shfl_xor_sync(0xffffffffu, rmax, off));
            const float mnew  = fmaxf(mrow[i], rmax);
            const float alpha = __expf(mrow[i] - mnew);
            mrow[i] = mnew;
            float rsum = 0.0f;
#pragma unroll
            for (int j = 0; j < 4; j++) {
                s[i][j] = __expf(s[i][j] - mnew);
                rsum += s[i][j];
            }
#pragma unroll
            for (int off = 8; off > 0; off >>= 1)
                rsum += __shfl_xor_sync(0xffffffffu, rsum, off);
            lrow[i] = lrow[i] * alpha + rsum;
#pragma unroll
            for (int j = 0; j < 4; j++)
                o[i][j] *= alpha;
        }

        // Stage P transposed: Pst[key][row]
#pragma unroll
        for (int i = 0; i < 4; i++)
#pragma unroll
            for (int j = 0; j < 4; j++)
                Pst[(tx * 4 + j) * AP + (ty * 4 + i)] = s[i][j];
        __syncthreads();

        // O += P @ V  (V = K tile, natural layout Kn[key][d])
#pragma unroll 16
        for (int kk = 0; kk < 64; kk++) {
            float4 a = *reinterpret_cast<const float4*>(&Pst[kk * AP + ty * 4]);
            float4 v = *reinterpret_cast<const float4*>(&Kn[kk * AP + tx * 4]);
            float aa[4] = {a.x, a.y, a.z, a.w};
            float bb[4] = {v.x, v.y, v.z, v.w};
#pragma unroll
            for (int i = 0; i < 4; i++)
#pragma unroll
                for (int j = 0; j < 4; j++)
                    o[i][j] = fmaf(aa[i], bb[j], o[i][j]);
        }
    }

    // Normalize and write out: [B,S,E] with head h at cols h*64..h*64+63
#pragma unroll
    for (int i = 0; i < 4; i++) {
        const float inv = 1.0f / lrow[i];
        const size_t row = (size_t)(b * SEQ + q0 + ty * 4 + i) * EDIM + h * HD;
#pragma unroll
        for (int j = 0; j < 4; j++)
            O[row + tx * 4 + j] = o[i][j] * inv;
    }
}

// ---------------------------------------------------------------------------
extern "C" void kernel_launch(void* const* d_in, const int* in_sizes, int n_in,
                              void* d_out, int out_size)
{
    const float* x  = (const float*)d_in[0];
    const float* Wq = (const float*)d_in[1];
    const float* bq = (const float*)d_in[2];
    const float* Wk = (const float*)d_in[3];
    const float* bk = (const float*)d_in[4];
    const float* Wo = (const float*)d_in[5];
    const float* bo = (const float*)d_in[6];
    float* out = (float*)d_out;

    float *Qb, *Kb, *Ob;
    cudaGetSymbolAddress((void**)&Qb, g_Q);
    cudaGetSymbolAddress((void**)&Kb, g_K);
    cudaGetSymbolAddress((void**)&Ob, g_O);

    cudaFuncSetAttribute(attn_kernel,
                         cudaFuncAttributeMaxDynamicSharedMemorySize,
                         ATTN_SMEM_BYTES);

    dim3 gblk(256);
    dim3 ggrid(EDIM / BN, MTOT / BM);   // (12, 128)

    // Q and K projections
    gemm_nt_bias<<<ggrid, gblk>>>(x, Wq, bq, Qb, MTOT, EDIM, EDIM);
    gemm_nt_bias<<<ggrid, gblk>>>(x, Wk, bk, Kb, MTOT, EDIM, EDIM);

    // Attention (V aliases K per the reference)
    dim3 agrid(SEQ / 64, NH, BATCH);    // (16, 12, 8)
    attn_kernel<<<agrid, 256, ATTN_SMEM_BYTES>>>(Qb, Kb, Ob);

    // Output projection
    gemm_nt_bias<<<ggrid, gblk>>>(Ob, Wo, bo, out, MTOT, EDIM, EDIM);
}

// round 3
// speedup vs baseline: 1.1651x; 1.1651x over previous
#include <cuda_runtime.h>
#include <cstddef>

#define EDIM   768
#define BATCH  8
#define SEQ    1024
#define NH     12
#define HD     64
#define MTOT   (BATCH * SEQ)   // 8192

// Scratch (no cudaMalloc allowed): Q, K projections and attention output.
__device__ float g_Q[(size_t)MTOT * EDIM];
__device__ float g_K[(size_t)MTOT * EDIM];
__device__ float g_O[(size_t)MTOT * EDIM];

// ---------------------------------------------------------------------------
// GEMM (NT): C[m][n] = sum_k A[m][k] * W[n][k] + bias[n]
// A: [M,K] row-major, W: [N,K] row-major.
// BM=BN=128, BK=16, 256 threads, 8x8 micro-tile.
// ---------------------------------------------------------------------------
#define BM 128
#define BN 128
#define BK 16
#define GP 132   // smem pitch (floats)

__global__ __launch_bounds__(256) void gemm_nt_bias(
    const float* __restrict__ A, const float* __restrict__ W,
    const float* __restrict__ bias, float* __restrict__ C,
    int M, int N, int K)
{
    __shared__ float As[BK][GP];  // As[k][m]
    __shared__ float Ws[BK][GP];  // Ws[k][n]

    const int tid = threadIdx.x;
    const int tx = tid & 15;          // n-dir, 8 cols each
    const int ty = tid >> 4;          // m-dir, 8 rows each
    const int m0 = blockIdx.y * BM;
    const int n0 = blockIdx.x * BN;

    const int r  = tid >> 2;          // 0..63
    const int c4 = (tid & 3) << 2;    // 0,4,8,12 (covers BK=16)

    const float* Ap0 = A + (size_t)(m0 + r)      * K + c4;
    const float* Ap1 = A + (size_t)(m0 + r + 64) * K + c4;
    const float* Wp0 = W + (size_t)(n0 + r)      * K + c4;
    const float* Wp1 = W + (size_t)(n0 + r + 64) * K + c4;

    float acc[8][8] = {};

    for (int k0 = 0; k0 < K; k0 += BK) {
        float4 av0 = *reinterpret_cast<const float4*>(Ap0 + k0);
        float4 av1 = *reinterpret_cast<const float4*>(Ap1 + k0);
        float4 wv0 = *reinterpret_cast<const float4*>(Wp0 + k0);
        float4 wv1 = *reinterpret_cast<const float4*>(Wp1 + k0);
        __syncthreads();
        As[c4 + 0][r] = av0.x; As[c4 + 1][r] = av0.y;
        As[c4 + 2][r] = av0.z; As[c4 + 3][r] = av0.w;
        As[c4 + 0][r + 64] = av1.x; As[c4 + 1][r + 64] = av1.y;
        As[c4 + 2][r + 64] = av1.z; As[c4 + 3][r + 64] = av1.w;
        Ws[c4 + 0][r] = wv0.x; Ws[c4 + 1][r] = wv0.y;
        Ws[c4 + 2][r] = wv0.z; Ws[c4 + 3][r] = wv0.w;
        Ws[c4 + 0][r + 64] = wv1.x; Ws[c4 + 1][r + 64] = wv1.y;
        Ws[c4 + 2][r + 64] = wv1.z; Ws[c4 + 3][r + 64] = wv1.w;
        __syncthreads();

#pragma unroll
        for (int k = 0; k < BK; k++) {
            float4 a0 = *reinterpret_cast<const float4*>(&As[k][ty * 8]);
            float4 a1 = *reinterpret_cast<const float4*>(&As[k][ty * 8 + 4]);
            float4 b0 = *reinterpret_cast<const float4*>(&Ws[k][tx * 8]);
            float4 b1 = *reinterpret_cast<const float4*>(&Ws[k][tx * 8 + 4]);
            float aa[8] = {a0.x, a0.y, a0.z, a0.w, a1.x, a1.y, a1.z, a1.w};
            float bb[8] = {b0.x, b0.y, b0.z, b0.w, b1.x, b1.y, b1.z, b1.w};
#pragma unroll
            for (int i = 0; i < 8; i++)
#pragma unroll
                for (int j = 0; j < 8; j++)
                    acc[i][j] = fmaf(aa[i], bb[j], acc[i][j]);
        }
    }

    float4 bv0 = *reinterpret_cast<const float4*>(&bias[n0 + tx * 8]);
    float4 bv1 = *reinterpret_cast<const float4*>(&bias[n0 + tx * 8 + 4]);
    const float bb[8] = {bv0.x, bv0.y, bv0.z, bv0.w, bv1.x, bv1.y, bv1.z, bv1.w};

#pragma unroll
    for (int i = 0; i < 8; i++) {
        const size_t m = (size_t)(m0 + ty * 8 + i);
        float4 o0 = make_float4(acc[i][0] + bb[0], acc[i][1] + bb[1],
                                acc[i][2] + bb[2], acc[i][3] + bb[3]);
        float4 o1 = make_float4(acc[i][4] + bb[4], acc[i][5] + bb[5],
                                acc[i][6] + bb[6], acc[i][7] + bb[7]);
        *reinterpret_cast<float4*>(&C[m * N + n0 + tx * 8])     = o0;
        *reinterpret_cast<float4*>(&C[m * N + n0 + tx * 8 + 4]) = o1;
    }
}

// ---------------------------------------------------------------------------
// Flash attention: one CTA per (qtile=128 rows, head, batch). V == K.
// 256 threads: ty (16) x 8 queries, tx (16) x 4 keys / 4 dims.
// smem: Qst[d][q] (scaled), Kst[d][key], Kn[key][d], Pst[key][q]
// ---------------------------------------------------------------------------
#define QT  128
#define KT  64
#define APQ 132
#define APK 68
#define ATTN_SMEM_FLOATS (HD * APQ + HD * APK + KT * APK + KT * APQ)
#define ATTN_SMEM_BYTES  (ATTN_SMEM_FLOATS * 4)

__global__ __launch_bounds__(256) void attn_kernel(
    const float* __restrict__ Q, const float* __restrict__ K,
    float* __restrict__ O)
{
    extern __shared__ float sm[];
    float* Qst = sm;                  // [HD][APQ]  Qst[d*APQ + q]
    float* Kst = Qst + HD * APQ;      // [HD][APK]  Kst[d*APK + key]
    float* Kn  = Kst + HD * APK;      // [KT][APK]  Kn[key*APK + d]
    float* Pst = Kn  + KT * APK;      // [KT][APQ]  Pst[key*APQ + q]

    const int tid = threadIdx.x;
    const int tx = tid & 15;
    const int ty = tid >> 4;
    const int qt = blockIdx.x;   // 0..7
    const int h  = blockIdx.y;   // 0..11
    const int b  = blockIdx.z;   // 0..7
    const float scale = 0.125f;  // 1/sqrt(64)

    const int r  = tid >> 2;          // 0..63
    const int d0 = (tid & 3) << 4;    // 0,16,32,48
    const int q0 = qt * QT;

    // Load Q tile (pre-scaled) into d-major layout: 128 rows x 64 dims.
#pragma unroll
    for (int rr = 0; rr < 2; rr++) {
        const int q = r + rr * 64;
        const float* qrow = &Q[((size_t)(b * SEQ + q0 + q)) * EDIM + h * HD];
#pragma unroll
        for (int c = 0; c < 4; c++) {
            const int d4 = d0 + c * 4;
            float4 qv = *reinterpret_cast<const float4*>(qrow + d4);
            Qst[(d4 + 0) * APQ + q] = qv.x * scale;
            Qst[(d4 + 1) * APQ + q] = qv.y * scale;
            Qst[(d4 + 2) * APQ + q] = qv.z * scale;
            Qst[(d4 + 3) * APQ + q] = qv.w * scale;
        }
    }

    float o[8][4] = {};
    float mrow[8], lrow[8];
#pragma unroll
    for (int i = 0; i < 8; i++) { mrow[i] = -1e30f; lrow[i] = 0.0f; }

    for (int kt = 0; kt < SEQ / KT; kt++) {
        __syncthreads();  // prev PV done with Kn/Pst; Q write visible (iter 0)
        // Load K tile (64 keys x 64 dims) into both layouts.
        {
            const float* krow = &K[((size_t)(b * SEQ + kt * KT + r)) * EDIM + h * HD];
#pragma unroll
            for (int c = 0; c < 4; c++) {
                const int d4 = d0 + c * 4;
                float4 kv = *reinterpret_cast<const float4*>(krow + d4);
                *reinterpret_cast<float4*>(&Kn[r * APK + d4]) = kv;
                Kst[(d4 + 0) * APK + r] = kv.x;
                Kst[(d4 + 1) * APK + r] = kv.y;
                Kst[(d4 + 2) * APK + r] = kv.z;
                Kst[(d4 + 3) * APK + r] = kv.w;
            }
        }
        __syncthreads();

        // S = (Q*scale) K^T : rows ty*8+i (query), cols tx*4+j (key)
        float s[8][4] = {};
#pragma unroll 8
        for (int d = 0; d < HD; d++) {
            float4 a0 = *reinterpret_cast<const float4*>(&Qst[d * APQ + ty * 8]);
            float4 a1 = *reinterpret_cast<const float4*>(&Qst[d * APQ + ty * 8 + 4]);
            float4 bv = *reinterpret_cast<const float4*>(&Kst[d * APK + tx * 4]);
            float aa[8] = {a0.x, a0.y, a0.z, a0.w, a1.x, a1.y, a1.z, a1.w};
            float kb[4] = {bv.x, bv.y, bv.z, bv.w};
#pragma unroll
            for (int i = 0; i < 8; i++)
#pragma unroll
                for (int j = 0; j < 4; j++)
                    s[i][j] = fmaf(aa[i], kb[j], s[i][j]);
        }

        // Online softmax per query row (16 tx-lanes hold a row's 64 keys).
#pragma unroll
        for (int i = 0; i < 8; i++) {
            float rmax = fmaxf(fmaxf(s[i][0], s[i][1]), fmaxf(s[i][2], s[i][3]));
#pragma unroll
            for (int off = 8; off > 0; off >>= 1)
                rmax = fmaxf(rmax, __shfl_xor_sync(0xffffffffu, rmax, off));
            const float mnew  = fmaxf(mrow[i], rmax);
            const float alpha = __expf(mrow[i] - mnew);
            mrow[i] = mnew;
            float rsum = 0.0f;
#pragma unroll
            for (int j = 0; j < 4; j++) {
                s[i][j] = __expf(s[i][j] - mnew);
                rsum += s[i][j];
            }
#pragma unroll
            for (int off = 8; off > 0; off >>= 1)
                rsum += __shfl_xor_sync(0xffffffffu, rsum, off);
            lrow[i] = lrow[i] * alpha + rsum;
#pragma unroll
            for (int j = 0; j < 4; j++)
                o[i][j] *= alpha;
        }

        // Stage P transposed: Pst[key][q]
#pragma unroll
        for (int j = 0; j < 4; j++)
#pragma unroll
            for (int i = 0; i < 8; i++)
                Pst[(tx * 4 + j) * APQ + (ty * 8 + i)] = s[i][j];
        __syncthreads();

        // O += P @ V  (V = K tile, natural layout Kn[key][d])
#pragma unroll 8
        for (int kk = 0; kk < KT; kk++) {
            float4 a0 = *reinterpret_cast<const float4*>(&Pst[kk * APQ + ty * 8]);
            float4 a1 = *reinterpret_cast<const float4*>(&Pst[kk * APQ + ty * 8 + 4]);
            float4 vv = *reinterpret_cast<const float4*>(&Kn[kk * APK + tx * 4]);
            float aa[8] = {a0.x, a0.y, a0.z, a0.w, a1.x, a1.y, a1.z, a1.w};
            float vb[4] = {vv.x, vv.y, vv.z, vv.w};
#pragma unroll
            for (int i = 0; i < 8; i++)
#pragma unroll
                for (int j = 0; j < 4; j++)
                    o[i][j] = fmaf(aa[i], vb[j], o[i][j]);
        }
    }

    // Normalize and write out: [B,S,E] with head h at cols h*64..h*64+63
#pragma unroll
    for (int i = 0; i < 8; i++) {
        const float inv = 1.0f / lrow[i];
        const size_t row = (size_t)(b * SEQ + q0 + ty * 8 + i) * EDIM + h * HD;
        float4 ov = make_float4(o[i][0] * inv, o[i][1] * inv,
                                o[i][2] * inv, o[i][3] * inv);
        *reinterpret_cast<float4*>(&O[row + tx * 4]) = ov;
    }
}

// ---------------------------------------------------------------------------
extern "C" void kernel_launch(void* const* d_in, const int* in_sizes, int n_in,
                              void* d_out, int out_size)
{
    const float* x  = (const float*)d_in[0];
    const float* Wq = (const float*)d_in[1];
    const float* bq = (const float*)d_in[2];
    const float* Wk = (const float*)d_in[3];
    const float* bk = (const float*)d_in[4];
    const float* Wo = (const float*)d_in[5];
    const float* bo = (const float*)d_in[6];
    float* out = (float*)d_out;

    float *Qb, *Kb, *Ob;
    cudaGetSymbolAddress((void**)&Qb, g_Q);
    cudaGetSymbolAddress((void**)&Kb, g_K);
    cudaGetSymbolAddress((void**)&Ob, g_O);

    cudaFuncSetAttribute(attn_kernel,
                         cudaFuncAttributeMaxDynamicSharedMemorySize,
                         ATTN_SMEM_BYTES);

    dim3 gblk(256);
    dim3 ggrid(EDIM / BN, MTOT / BM);   // (6, 64)

    // Q and K projections
    gemm_nt_bias<<<ggrid, gblk>>>(x, Wq, bq, Qb, MTOT, EDIM, EDIM);
    gemm_nt_bias<<<ggrid, gblk>>>(x, Wk, bk, Kb, MTOT, EDIM, EDIM);

    // Attention (V aliases K per the reference)
    dim3 agrid(SEQ / QT, NH, BATCH);    // (8, 12, 8)
    attn_kernel<<<agrid, 256, ATTN_SMEM_BYTES>>>(Qb, Kb, Ob);

    // Output projection
    gemm_nt_bias<<<ggrid, gblk>>>(Ob, Wo, bo, out, MTOT, EDIM, EDIM);
}

// round 4
// speedup vs baseline: 1.2330x; 1.0583x over previous
#include <cuda_runtime.h>
#include <cstddef>
#include <cstdint>

#define EDIM   768
#define BATCH  8
#define SEQ    1024
#define NH     12
#define HD     64
#define MTOT   (BATCH * SEQ)   // 8192

// Scratch (no cudaMalloc allowed): Q, K projections and attention output.
__device__ float g_Q[(size_t)MTOT * EDIM];
__device__ float g_K[(size_t)MTOT * EDIM];
__device__ float g_O[(size_t)MTOT * EDIM];

// ---------------------------------------------------------------------------
// tf32 helpers
// ---------------------------------------------------------------------------
__device__ __forceinline__ void tf32_split(float x, uint32_t& hi, uint32_t& lo)
{
    uint32_t h;
    asm("cvt.rna.tf32.f32 %0, %1;" : "=r"(h) : "f"(x));
    float r = x - __uint_as_float(h);
    uint32_t l;
    asm("cvt.rna.tf32.f32 %0, %1;" : "=r"(l) : "f"(r));
    hi = h; lo = l;
}

__device__ __forceinline__ void mma_tf32(float* d, const uint32_t* a, const uint32_t* b)
{
    asm volatile(
        "mma.sync.aligned.m16n8k8.row.col.f32.tf32.tf32.f32 "
        "{%0,%1,%2,%3}, {%4,%5,%6,%7}, {%8,%9}, {%0,%1,%2,%3};\n"
        : "+f"(d[0]), "+f"(d[1]), "+f"(d[2]), "+f"(d[3])
        : "r"(a[0]), "r"(a[1]), "r"(a[2]), "r"(a[3]),
          "r"(b[0]), "r"(b[1]));
}

// ---------------------------------------------------------------------------
// GEMM (NT) via tf32 tensor cores + 3xTF32 split:
// C[m][n] = sum_k A[m][k] * W[n][k] + bias[n]
// CTA 128x128, BK=32, 8 warps (2m x 4n), warp tile 64x32.
// ---------------------------------------------------------------------------
#define BM 128
#define BN 128
#define BK 32
#define SP 36   // smem pitch: (36*row + k) % 32 == (4*row + k) % 32 -> conflict-free frags

__global__ __launch_bounds__(256) void gemm_tf32_bias(
    const float* __restrict__ A, const float* __restrict__ W,
    const float* __restrict__ bias, float* __restrict__ C,
    int M, int N, int K)
{
    __shared__ float As[BM][SP];   // As[m][k]
    __shared__ float Ws[BN][SP];   // Ws[n][k]

    const int tid  = threadIdx.x;
    const int warp = tid >> 5;
    const int lane = tid & 31;
    const int g    = lane >> 2;   // groupID 0..7
    const int t    = lane & 3;    // threadInGroup 0..3

    const int wm = (warp & 1) * 64;   // warp m-offset in tile
    const int wn = (warp >> 1) * 32;  // warp n-offset in tile

    const int m0 = blockIdx.y * BM;
    const int n0 = blockIdx.x * BN;

    // gmem load mapping: 8 threads per 32-float row
    const int lr = tid >> 3;         // 0..31 row within 32-row group
    const int lc = (tid & 7) * 4;    // float4 col within 32-float k slab

    float acc[4][4][4];
#pragma unroll
    for (int i = 0; i < 4; i++)
#pragma unroll
        for (int j = 0; j < 4; j++)
#pragma unroll
            for (int c = 0; c < 4; c++) acc[i][j][c] = 0.0f;

    for (int k0 = 0; k0 < K; k0 += BK) {
        float4 av[4], wv[4];
#pragma unroll
        for (int i = 0; i < 4; i++) {
            av[i] = *reinterpret_cast<const float4*>(
                &A[(size_t)(m0 + lr + i * 32) * K + k0 + lc]);
            wv[i] = *reinterpret_cast<const float4*>(
                &W[(size_t)(n0 + lr + i * 32) * K + k0 + lc]);
        }
        __syncthreads();
#pragma unroll
        for (int i = 0; i < 4; i++) {
            *reinterpret_cast<float4*>(&As[lr + i * 32][lc]) = av[i];
            *reinterpret_cast<float4*>(&Ws[lr + i * 32][lc]) = wv[i];
        }
        __syncthreads();

#pragma unroll
        for (int kk = 0; kk < BK; kk += 8) {
            uint32_t ah[4][4], al[4][4], bh[4][2], bl[4][2];
#pragma unroll
            for (int mt = 0; mt < 4; mt++) {
                const int r0 = wm + mt * 16 + g;
                tf32_split(As[r0    ][kk + t    ], ah[mt][0], al[mt][0]);
                tf32_split(As[r0 + 8][kk + t    ], ah[mt][1], al[mt][1]);
                tf32_split(As[r0    ][kk + t + 4], ah[mt][2], al[mt][2]);
                tf32_split(As[r0 + 8][kk + t + 4], ah[mt][3], al[mt][3]);
            }
#pragma unroll
            for (int nt = 0; nt < 4; nt++) {
                const int c0 = wn + nt * 8 + g;
                tf32_split(Ws[c0][kk + t    ], bh[nt][0], bl[nt][0]);
                tf32_split(Ws[c0][kk + t + 4], bh[nt][1], bl[nt][1]);
            }
#pragma unroll
            for (int mt = 0; mt < 4; mt++)
#pragma unroll
                for (int nt = 0; nt < 4; nt++) {
                    mma_tf32(acc[mt][nt], ah[mt], bh[nt]);
                    mma_tf32(acc[mt][nt], ah[mt], bl[nt]);
                    mma_tf32(acc[mt][nt], al[mt], bh[nt]);
                }
        }
    }

    // Epilogue: c0=(g,2t) c1=(g,2t+1) c2=(g+8,2t) c3=(g+8,2t+1)
#pragma unroll
    for (int nt = 0; nt < 4; nt++) {
        const int n = n0 + wn + nt * 8 + 2 * t;
        const float2 bv = *reinterpret_cast<const float2*>(&bias[n]);
#pragma unroll
        for (int mt = 0; mt < 4; mt++) {
            const size_t r0 = (size_t)(m0 + wm + mt * 16 + g);
            const size_t r1 = r0 + 8;
            float2 o0 = make_float2(acc[mt][nt][0] + bv.x, acc[mt][nt][1] + bv.y);
            float2 o1 = make_float2(acc[mt][nt][2] + bv.x, acc[mt][nt][3] + bv.y);
            *reinterpret_cast<float2*>(&C[r0 * N + n]) = o0;
            *reinterpret_cast<float2*>(&C[r1 * N + n]) = o1;
        }
    }
}

// ---------------------------------------------------------------------------
// Flash attention: one CTA per (qtile=128 rows, head, batch). V == K.
// 256 threads: ty (16) x 8 queries, tx (16) x 4 keys / 4 dims.
// smem: Qst[d][q] (scaled), Kst[d][key], Kn[key][d], Pst[key][q]
// ---------------------------------------------------------------------------
#define QT  128
#define KT  64
#define APQ 132
#define APK 68
#define ATTN_SMEM_FLOATS (HD * APQ + HD * APK + KT * APK + KT * APQ)
#define ATTN_SMEM_BYTES  (ATTN_SMEM_FLOATS * 4)

__global__ __launch_bounds__(256) void attn_kernel(
    const float* __restrict__ Q, const float* __restrict__ K,
    float* __restrict__ O)
{
    extern __shared__ float sm[];
    float* Qst = sm;                  // [HD][APQ]  Qst[d*APQ + q]
    float* Kst = Qst + HD * APQ;      // [HD][APK]  Kst[d*APK + key]
    float* Kn  = Kst + HD * APK;      // [KT][APK]  Kn[key*APK + d]
    float* Pst = Kn  + KT * APK;      // [KT][APQ]  Pst[key*APQ + q]

    const int tid = threadIdx.x;
    const int tx = tid & 15;
    const int ty = tid >> 4;
    const int qt = blockIdx.x;   // 0..7
    const int h  = blockIdx.y;   // 0..11
    const int b  = blockIdx.z;   // 0..7
    const float scale = 0.125f;  // 1/sqrt(64)

    const int r  = tid >> 2;          // 0..63
    const int d0 = (tid & 3) << 4;    // 0,16,32,48
    const int q0 = qt * QT;

    // Load Q tile (pre-scaled) into d-major layout: 128 rows x 64 dims.
#pragma unroll
    for (int rr = 0; rr < 2; rr++) {
        const int q = r + rr * 64;
        const float* qrow = &Q[((size_t)(b * SEQ + q0 + q)) * EDIM + h * HD];
#pragma unroll
        for (int c = 0; c < 4; c++) {
            const int d4 = d0 + c * 4;
            float4 qv = *reinterpret_cast<const float4*>(qrow + d4);
            Qst[(d4 + 0) * APQ + q] = qv.x * scale;
            Qst[(d4 + 1) * APQ + q] = qv.y * scale;
            Qst[(d4 + 2) * APQ + q] = qv.z * scale;
            Qst[(d4 + 3) * APQ + q] = qv.w * scale;
        }
    }

    float o[8][4] = {};
    float mrow[8], lrow[8];
#pragma unroll
    for (int i = 0; i < 8; i++) { mrow[i] = -1e30f; lrow[i] = 0.0f; }

    for (int kt = 0; kt < SEQ / KT; kt++) {
        __syncthreads();  // prev PV done with Kn/Pst; Q write visible (iter 0)
        // Load K tile (64 keys x 64 dims) into both layouts.
        {
            const float* krow = &K[((size_t)(b * SEQ + kt * KT + r)) * EDIM + h * HD];
#pragma unroll
            for (int c = 0; c < 4; c++) {
                const int d4 = d0 + c * 4;
                float4 kv = *reinterpret_cast<const float4*>(krow + d4);
                *reinterpret_cast<float4*>(&Kn[r * APK + d4]) = kv;
                Kst[(d4 + 0) * APK + r] = kv.x;
                Kst[(d4 + 1) * APK + r] = kv.y;
                Kst[(d4 + 2) * APK + r] = kv.z;
                Kst[(d4 + 3) * APK + r] = kv.w;
            }
        }
        __syncthreads();

        // S = (Q*scale) K^T : rows ty*8+i (query), cols tx*4+j (key)
        float s[8][4] = {};
#pragma unroll 8
        for (int d = 0; d < HD; d++) {
            float4 a0 = *reinterpret_cast<const float4*>(&Qst[d * APQ + ty * 8]);
            float4 a1 = *reinterpret_cast<const float4*>(&Qst[d * APQ + ty * 8 + 4]);
            float4 bv = *reinterpret_cast<const float4*>(&Kst[d * APK + tx * 4]);
            float aa[8] = {a0.x, a0.y, a0.z, a0.w, a1.x, a1.y, a1.z, a1.w};
            float kb[4] = {bv.x, bv.y, bv.z, bv.w};
#pragma unroll
            for (int i = 0; i < 8; i++)
#pragma unroll
                for (int j = 0; j < 4; j++)
                    s[i][j] = fmaf(aa[i], kb[j], s[i][j]);
        }

        // Online softmax per query row (16 tx-lanes hold a row's 64 keys).
#pragma unroll
        for (int i = 0; i < 8; i++) {
            float rmax = fmaxf(fmaxf(s[i][0], s[i][1]), fmaxf(s[i][2], s[i][3]));
#pragma unroll
            for (int off = 8; off > 0; off >>= 1)
                rmax = fmaxf(rmax, __shfl_xor_sync(0xffffffffu, rmax, off));
            const float mnew  = fmaxf(mrow[i], rmax);
            const float alpha = __expf(mrow[i] - mnew);
            mrow[i] = mnew;
            float rsum = 0.0f;
#pragma unroll
            for (int j = 0; j < 4; j++) {
                s[i][j] = __expf(s[i][j] - mnew);
                rsum += s[i][j];
            }
#pragma unroll
            for (int off = 8; off > 0; off >>= 1)
                rsum += __shfl_xor_sync(0xffffffffu, rsum, off);
            lrow[i] = lrow[i] * alpha + rsum;
#pragma unroll
            for (int j = 0; j < 4; j++)
                o[i][j] *= alpha;
        }

        // Stage P transposed: Pst[key][q]
#pragma unroll
        for (int j = 0; j < 4; j++)
#pragma unroll
            for (int i = 0; i < 8; i++)
                Pst[(tx * 4 + j) * APQ + (ty * 8 + i)] = s[i][j];
        __syncthreads();

        // O += P @ V  (V = K tile, natural layout Kn[key][d])
#pragma unroll 8
        for (int kk = 0; kk < KT; kk++) {
            float4 a0 = *reinterpret_cast<const float4*>(&Pst[kk * APQ + ty * 8]);
            float4 a1 = *reinterpret_cast<const float4*>(&Pst[kk * APQ + ty * 8 + 4]);
            float4 vv = *reinterpret_cast<const float4*>(&Kn[kk * APK + tx * 4]);
            float aa[8] = {a0.x, a0.y, a0.z, a0.w, a1.x, a1.y, a1.z, a1.w};
            float vb[4] = {vv.x, vv.y, vv.z, vv.w};
#pragma unroll
            for (int i = 0; i < 8; i++)
#pragma unroll
                for (int j = 0; j < 4; j++)
                    o[i][j] = fmaf(aa[i], vb[j], o[i][j]);
        }
    }

    // Normalize and write out: [B,S,E] with head h at cols h*64..h*64+63
#pragma unroll
    for (int i = 0; i < 8; i++) {
        const float inv = 1.0f / lrow[i];
        const size_t row = (size_t)(b * SEQ + q0 + ty * 8 + i) * EDIM + h * HD;
        float4 ov = make_float4(o[i][0] * inv, o[i][1] * inv,
                                o[i][2] * inv, o[i][3] * inv);
        *reinterpret_cast<float4*>(&O[row + tx * 4]) = ov;
    }
}

// ---------------------------------------------------------------------------
extern "C" void kernel_launch(void* const* d_in, const int* in_sizes, int n_in,
                              void* d_out, int out_size)
{
    const float* x  = (const float*)d_in[0];
    const float* Wq = (const float*)d_in[1];
    const float* bq = (const float*)d_in[2];
    const float* Wk = (const float*)d_in[3];
    const float* bk = (const float*)d_in[4];
    const float* Wo = (const float*)d_in[5];
    const float* bo = (const float*)d_in[6];
    float* out = (float*)d_out;

    float *Qb, *Kb, *Ob;
    cudaGetSymbolAddress((void**)&Qb, g_Q);
    cudaGetSymbolAddress((void**)&Kb, g_K);
    cudaGetSymbolAddress((void**)&Ob, g_O);

    cudaFuncSetAttribute(attn_kernel,
                         cudaFuncAttributeMaxDynamicSharedMemorySize,
                         ATTN_SMEM_BYTES);

    dim3 gblk(256);
    dim3 ggrid(EDIM / BN, MTOT / BM);   // (6, 64)

    // Q and K projections
    gemm_tf32_bias<<<ggrid, gblk>>>(x, Wq, bq, Qb, MTOT, EDIM, EDIM);
    gemm_tf32_bias<<<ggrid, gblk>>>(x, Wk, bk, Kb, MTOT, EDIM, EDIM);

    // Attention (V aliases K per the reference)
    dim3 agrid(SEQ / QT, NH, BATCH);    // (8, 12, 8)
    attn_kernel<<<agrid, 256, ATTN_SMEM_BYTES>>>(Qb, Kb, Ob);

    // Output projection
    gemm_tf32_bias<<<ggrid, gblk>>>(Ob, Wo, bo, out, MTOT, EDIM, EDIM);
}

// round 5
// speedup vs baseline: 1.5539x; 1.2602x over previous
#include <cuda_runtime.h>
#include <cstddef>
#include <cstdint>

#define EDIM   768
#define BATCH  8
#define SEQ    1024
#define NH     12
#define HD     64
#define MTOT   (BATCH * SEQ)   // 8192

// Scratch (no cudaMalloc allowed): Q, K projections and attention output.
__device__ float g_Q[(size_t)MTOT * EDIM];
__device__ float g_K[(size_t)MTOT * EDIM];
__device__ float g_O[(size_t)MTOT * EDIM];

// ---------------------------------------------------------------------------
// tf32 helpers
// ---------------------------------------------------------------------------
__device__ __forceinline__ void tf32_split(float x, uint32_t& hi, uint32_t& lo)
{
    uint32_t h;
    asm("cvt.rna.tf32.f32 %0, %1;" : "=r"(h) : "f"(x));
    float r = x - __uint_as_float(h);
    uint32_t l;
    asm("cvt.rna.tf32.f32 %0, %1;" : "=r"(l) : "f"(r));
    hi = h; lo = l;
}

__device__ __forceinline__ uint32_t tf32_cvt(float x)
{
    uint32_t h;
    asm("cvt.rna.tf32.f32 %0, %1;" : "=r"(h) : "f"(x));
    return h;
}

__device__ __forceinline__ void mma_tf32(float* d, const uint32_t* a, const uint32_t* b)
{
    asm volatile(
        "mma.sync.aligned.m16n8k8.row.col.f32.tf32.tf32.f32 "
        "{%0,%1,%2,%3}, {%4,%5,%6,%7}, {%8,%9}, {%0,%1,%2,%3};\n"
        : "+f"(d[0]), "+f"(d[1]), "+f"(d[2]), "+f"(d[3])
        : "r"(a[0]), "r"(a[1]), "r"(a[2]), "r"(a[3]),
          "r"(b[0]), "r"(b[1]));
}

// ---------------------------------------------------------------------------
// GEMM (NT) via tf32 tensor cores + 3xTF32 split:
// C[m][n] = sum_k A[m][k] * W[n][k] + bias[n]
// CTA 128x128, BK=32, 8 warps (2m x 4n), warp tile 64x32.
// MMA issue in 3 passes (hh, hl, lh) so same-acc reuse distance = 16.
// ---------------------------------------------------------------------------
#define BM 128
#define BN 128
#define BK 32
#define SP 36   // smem pitch: (36*row + k) % 32 == (4*row + k) % 32 -> conflict-free frags

__global__ __launch_bounds__(256) void gemm_tf32_bias(
    const float* __restrict__ A, const float* __restrict__ W,
    const float* __restrict__ bias, float* __restrict__ C,
    int M, int N, int K)
{
    __shared__ float As[BM][SP];   // As[m][k]
    __shared__ float Ws[BN][SP];   // Ws[n][k]

    const int tid  = threadIdx.x;
    const int warp = tid >> 5;
    const int lane = tid & 31;
    const int g    = lane >> 2;   // groupID 0..7
    const int t    = lane & 3;    // threadInGroup 0..3

    const int wm = (warp & 1) * 64;   // warp m-offset in tile
    const int wn = (warp >> 1) * 32;  // warp n-offset in tile

    const int m0 = blockIdx.y * BM;
    const int n0 = blockIdx.x * BN;

    // gmem load mapping: 8 threads per 32-float row
    const int lr = tid >> 3;         // 0..31 row within 32-row group
    const int lc = (tid & 7) * 4;    // float4 col within 32-float k slab

    float acc[4][4][4];
#pragma unroll
    for (int i = 0; i < 4; i++)
#pragma unroll
        for (int j = 0; j < 4; j++)
#pragma unroll
            for (int c = 0; c < 4; c++) acc[i][j][c] = 0.0f;

    for (int k0 = 0; k0 < K; k0 += BK) {
        float4 av[4], wv[4];
#pragma unroll
        for (int i = 0; i < 4; i++) {
            av[i] = *reinterpret_cast<const float4*>(
                &A[(size_t)(m0 + lr + i * 32) * K + k0 + lc]);
            wv[i] = *reinterpret_cast<const float4*>(
                &W[(size_t)(n0 + lr + i * 32) * K + k0 + lc]);
        }
        __syncthreads();
#pragma unroll
        for (int i = 0; i < 4; i++) {
            *reinterpret_cast<float4*>(&As[lr + i * 32][lc]) = av[i];
            *reinterpret_cast<float4*>(&Ws[lr + i * 32][lc]) = wv[i];
        }
        __syncthreads();

#pragma unroll
        for (int kk = 0; kk < BK; kk += 8) {
            uint32_t ah[4][4], al[4][4], bh[4][2], bl[4][2];
#pragma unroll
            for (int mt = 0; mt < 4; mt++) {
                const int r0 = wm + mt * 16 + g;
                tf32_split(As[r0    ][kk + t    ], ah[mt][0], al[mt][0]);
                tf32_split(As[r0 + 8][kk + t    ], ah[mt][1], al[mt][1]);
                tf32_split(As[r0    ][kk + t + 4], ah[mt][2], al[mt][2]);
                tf32_split(As[r0 + 8][kk + t + 4], ah[mt][3], al[mt][3]);
            }
#pragma unroll
            for (int nt = 0; nt < 4; nt++) {
                const int c0 = wn + nt * 8 + g;
                tf32_split(Ws[c0][kk + t    ], bh[nt][0], bl[nt][0]);
                tf32_split(Ws[c0][kk + t + 4], bh[nt][1], bl[nt][1]);
            }
            // 3 passes: each pass has 16 independent MMAs.
#pragma unroll
            for (int mt = 0; mt < 4; mt++)
#pragma unroll
                for (int nt = 0; nt < 4; nt++)
                    mma_tf32(acc[mt][nt], ah[mt], bh[nt]);
#pragma unroll
            for (int mt = 0; mt < 4; mt++)
#pragma unroll
                for (int nt = 0; nt < 4; nt++)
                    mma_tf32(acc[mt][nt], ah[mt], bl[nt]);
#pragma unroll
            for (int mt = 0; mt < 4; mt++)
#pragma unroll
                for (int nt = 0; nt < 4; nt++)
                    mma_tf32(acc[mt][nt], al[mt], bh[nt]);
        }
    }

    // Epilogue: c0=(g,2t) c1=(g,2t+1) c2=(g+8,2t) c3=(g+8,2t+1)
#pragma unroll
    for (int nt = 0; nt < 4; nt++) {
        const int n = n0 + wn + nt * 8 + 2 * t;
        const float2 bv = *reinterpret_cast<const float2*>(&bias[n]);
#pragma unroll
        for (int mt = 0; mt < 4; mt++) {
            const size_t r0 = (size_t)(m0 + wm + mt * 16 + g);
            const size_t r1 = r0 + 8;
            float2 o0 = make_float2(acc[mt][nt][0] + bv.x, acc[mt][nt][1] + bv.y);
            float2 o1 = make_float2(acc[mt][nt][2] + bv.x, acc[mt][nt][3] + bv.y);
            *reinterpret_cast<float2*>(&C[r0 * N + n]) = o0;
            *reinterpret_cast<float2*>(&C[r1 * N + n]) = o1;
        }
    }
}

// ---------------------------------------------------------------------------
// Flash attention via mma.sync tf32. One CTA per (128 queries, head, batch).
// 8 warps, each owns 16 query rows. V == K (reference bug).
// K tile [64 keys][64 d] stored once (hi/lo tf32) serves both QK^T and PV.
// QK^T: single tf32 (scores need little precision). PV: 3xTF32 split.
// ---------------------------------------------------------------------------
#define PIT 68   // smem pitch (words): 68 % 32 == 4 -> (4g + t) patterns conflict-free
#define ATTN_SMEM_WORDS (2 * 128 * PIT + 2 * 64 * PIT)
#define ATTN_SMEM_BYTES (ATTN_SMEM_WORDS * 4)

__global__ __launch_bounds__(256) void attn_mma(
    const float* __restrict__ Q, const float* __restrict__ K,
    float* __restrict__ O)
{
    extern __shared__ uint32_t smu[];
    float*    Qn = reinterpret_cast<float*>(smu);   // [128][PIT] prescaled Q, [q][d]
    float*    Ps = Qn + 128 * PIT;                  // [128][PIT] probabilities, [q][key]
    uint32_t* Kh = smu + 2 * 128 * PIT;             // [64][PIT] tf32-hi of K, [key][d]
    uint32_t* Kl = Kh + 64 * PIT;                   // [64][PIT] tf32-lo of K

    const int tid  = threadIdx.x;
    const int warp = tid >> 5;
    const int lane = tid & 31;
    const int g = lane >> 2, t = lane & 3;
    const int wq = warp * 16;                       // warp's query-row base

    const int qt = blockIdx.x, h = blockIdx.y, b = blockIdx.z;
    const int q0 = qt * 128;

    // Load Q tile (prescaled by 1/sqrt(64)) into [q][d] natural layout.
    {
        const int r  = tid >> 1;
        const int dc = (tid & 1) * 32;
        const float* src = &Q[((size_t)(b * SEQ + q0 + r)) * EDIM + h * HD + dc];
        float* dst = &Qn[r * PIT + dc];
#pragma unroll
        for (int c = 0; c < 8; c++) {
            float4 v = *reinterpret_cast<const float4*>(src + c * 4);
            *reinterpret_cast<float4*>(dst + c * 4) =
                make_float4(v.x * 0.125f, v.y * 0.125f, v.z * 0.125f, v.w * 0.125f);
        }
    }

    float o[8][4];
#pragma unroll
    for (int i = 0; i < 8; i++)
#pragma unroll
        for (int j = 0; j < 4; j++) o[i][j] = 0.0f;
    float m0 = -1e30f, m1 = -1e30f, l0 = 0.0f, l1 = 0.0f;

    const int kr = tid >> 2;        // 0..63 key row
    const int kd = (tid & 3) << 4;  // 0,16,32,48 d-chunk base

    for (int kt = 0; kt < SEQ / 64; kt++) {
        // Stage next K tile (gmem loads issued before the barrier).
        float4 kv[4];
        const float* krow = &K[((size_t)(b * SEQ + kt * 64 + kr)) * EDIM + h * HD + kd];
#pragma unroll
        for (int c = 0; c < 4; c++)
            kv[c] = *reinterpret_cast<const float4*>(krow + c * 4);

        __syncthreads();  // all warps done reading Kh/Kl (and Qn store visible, iter 0)
#pragma unroll
        for (int c = 0; c < 4; c++) {
            uint32_t hi0, lo0, hi1, lo1, hi2, lo2, hi3, lo3;
            tf32_split(kv[c].x, hi0, lo0);
            tf32_split(kv[c].y, hi1, lo1);
            tf32_split(kv[c].z, hi2, lo2);
            tf32_split(kv[c].w, hi3, lo3);
            *reinterpret_cast<uint4*>(&Kh[kr * PIT + kd + c * 4]) = make_uint4(hi0, hi1, hi2, hi3);
            *reinterpret_cast<uint4*>(&Kl[kr * PIT + kd + c * 4]) = make_uint4(lo0, lo1, lo2, lo3);
        }
        __syncthreads();

        // ---- S = (Q*scale) K^T, single tf32 ----
        float s[8][4];
#pragma unroll
        for (int i = 0; i < 8; i++)
#pragma unroll
            for (int j = 0; j < 4; j++) s[i][j] = 0.0f;

#pragma unroll
        for (int kk = 0; kk < 8; kk++) {
            const int ak = kk * 8 + t;   // d index
            uint32_t a[4];
            a[0] = tf32_cvt(Qn[(wq + g    ) * PIT + ak    ]);
            a[1] = tf32_cvt(Qn[(wq + g + 8) * PIT + ak    ]);
            a[2] = tf32_cvt(Qn[(wq + g    ) * PIT + ak + 4]);
            a[3] = tf32_cvt(Qn[(wq + g + 8) * PIT + ak + 4]);
#pragma unroll
            for (int nt = 0; nt < 8; nt++) {
                uint32_t bb[2];
                bb[0] = Kh[(nt * 8 + g) * PIT + ak    ];
                bb[1] = Kh[(nt * 8 + g) * PIT + ak + 4];
                mma_tf32(s[nt], a, bb);
            }
        }

        // ---- online softmax (rows g and g+8 of warp tile; quad holds a row) ----
        float rmax0 = -1e30f, rmax1 = -1e30f;
#pragma unroll
        for (int nt = 0; nt < 8; nt++) {
            rmax0 = fmaxf(rmax0, fmaxf(s[nt][0], s[nt][1]));
            rmax1 = fmaxf(rmax1, fmaxf(s[nt][2], s[nt][3]));
        }
#pragma unroll
        for (int off = 1; off <= 2; off <<= 1) {
            rmax0 = fmaxf(rmax0, __shfl_xor_sync(0xffffffffu, rmax0, off));
            rmax1 = fmaxf(rmax1, __shfl_xor_sync(0xffffffffu, rmax1, off));
        }
        const float mn0 = fmaxf(m0, rmax0);
        const float mn1 = fmaxf(m1, rmax1);
        const float al0 = __expf(m0 - mn0);
        const float al1 = __expf(m1 - mn1);
        m0 = mn0; m1 = mn1;

        float sum0 = 0.0f, sum1 = 0.0f;
#pragma unroll
        for (int nt = 0; nt < 8; nt++) {
            s[nt][0] = __expf(s[nt][0] - mn0);
            s[nt][1] = __expf(s[nt][1] - mn0);
            s[nt][2] = __expf(s[nt][2] - mn1);
            s[nt][3] = __expf(s[nt][3] - mn1);
            sum0 += s[nt][0] + s[nt][1];
            sum1 += s[nt][2] + s[nt][3];
        }
#pragma unroll
        for (int off = 1; off <= 2; off <<= 1) {
            sum0 += __shfl_xor_sync(0xffffffffu, sum0, off);
            sum1 += __shfl_xor_sync(0xffffffffu, sum1, off);
        }
        l0 = l0 * al0 + sum0;
        l1 = l1 * al1 + sum1;
#pragma unroll
        for (int nd = 0; nd < 8; nd++) {
            o[nd][0] *= al0; o[nd][1] *= al0;
            o[nd][2] *= al1; o[nd][3] *= al1;
        }

        // ---- stage P to smem [q][key] (own warp's 16 rows only) ----
#pragma unroll
        for (int nt = 0; nt < 8; nt++) {
            *reinterpret_cast<float2*>(&Ps[(wq + g    ) * PIT + nt * 8 + 2 * t]) =
                make_float2(s[nt][0], s[nt][1]);
            *reinterpret_cast<float2*>(&Ps[(wq + g + 8) * PIT + nt * 8 + 2 * t]) =
                make_float2(s[nt][2], s[nt][3]);
        }
        __syncwarp();

        // ---- O += P @ V (V = K tile), 3xTF32, 4-independent chunks ----
#pragma unroll
        for (int kk = 0; kk < 8; kk++) {
            const int pk = kk * 8 + t;   // key index
            uint32_t pah[4], pal[4];
            tf32_split(Ps[(wq + g    ) * PIT + pk    ], pah[0], pal[0]);
            tf32_split(Ps[(wq + g + 8) * PIT + pk    ], pah[1], pal[1]);
            tf32_split(Ps[(wq + g    ) * PIT + pk + 4], pah[2], pal[2]);
            tf32_split(Ps[(wq + g + 8) * PIT + pk + 4], pah[3], pal[3]);
#pragma unroll
            for (int c = 0; c < 2; c++) {
                uint32_t bh_[4][2], bl_[4][2];
#pragma unroll
                for (int i = 0; i < 4; i++) {
                    const int nd = c * 4 + i;
                    bh_[i][0] = Kh[(pk    ) * PIT + nd * 8 + g];
                    bh_[i][1] = Kh[(pk + 4) * PIT + nd * 8 + g];
                    bl_[i][0] = Kl[(pk    ) * PIT + nd * 8 + g];
                    bl_[i][1] = Kl[(pk + 4) * PIT + nd * 8 + g];
                }
#pragma unroll
                for (int i = 0; i < 4; i++) mma_tf32(o[c * 4 + i], pah, bh_[i]);
#pragma unroll
                for (int i = 0; i < 4; i++) mma_tf32(o[c * 4 + i], pah, bl_[i]);
#pragma unroll
                for (int i = 0; i < 4; i++) mma_tf32(o[c * 4 + i], pal, bh_[i]);
            }
        }
    }

    // ---- normalize and write [B,S,E] ----
    const float inv0 = 1.0f / l0;
    const float inv1 = 1.0f / l1;
    const size_t row0 = (size_t)(b * SEQ + q0 + wq + g) * EDIM + h * HD;
    const size_t row1 = row0 + (size_t)8 * EDIM;
#pragma unroll
    for (int nd = 0; nd < 8; nd++) {
        const int col = nd * 8 + 2 * t;
        *reinterpret_cast<float2*>(&O[row0 + col]) =
            make_float2(o[nd][0] * inv0, o[nd][1] * inv0);
        *reinterpret_cast<float2*>(&O[row1 + col]) =
            make_float2(o[nd][2] * inv1, o[nd][3] * inv1);
    }
}

// ---------------------------------------------------------------------------
extern "C" void kernel_launch(void* const* d_in, const int* in_sizes, int n_in,
                              void* d_out, int out_size)
{
    const float* x  = (const float*)d_in[0];
    const float* Wq = (const float*)d_in[1];
    const float* bq = (const float*)d_in[2];
    const float* Wk = (const float*)d_in[3];
    const float* bk = (const float*)d_in[4];
    const float* Wo = (const float*)d_in[5];
    const float* bo = (const float*)d_in[6];
    float* out = (float*)d_out;

    float *Qb, *Kb, *Ob;
    cudaGetSymbolAddress((void**)&Qb, g_Q);
    cudaGetSymbolAddress((void**)&Kb, g_K);
    cudaGetSymbolAddress((void**)&Ob, g_O);

    cudaFuncSetAttribute(attn_mma,
                         cudaFuncAttributeMaxDynamicSharedMemorySize,
                         ATTN_SMEM_BYTES);

    dim3 gblk(256);
    dim3 ggrid(EDIM / BN, MTOT / BM);   // (6, 64)

    // Q and K projections
    gemm_tf32_bias<<<ggrid, gblk>>>(x, Wq, bq, Qb, MTOT, EDIM, EDIM);
    gemm_tf32_bias<<<ggrid, gblk>>>(x, Wk, bk, Kb, MTOT, EDIM, EDIM);

    // Attention (V aliases K per the reference)
    dim3 agrid(SEQ / 128, NH, BATCH);   // (8, 12, 8)
    attn_mma<<<agrid, 256, ATTN_SMEM_BYTES>>>(Qb, Kb, Ob);

    // Output projection
    gemm_tf32_bias<<<ggrid, gblk>>>(Ob, Wo, bo, out, MTOT, EDIM, EDIM);
}

// round 6
// speedup vs baseline: 2.8359x; 1.8251x over previous
#include <cuda_runtime.h>
#include <cstddef>
#include <cstdint>

#define EDIM   768
#define BATCH  8
#define SEQ    1024
#define NH     12
#define HD     64
#define MTOT   (BATCH * SEQ)   // 8192

// Scratch (no cudaMalloc allowed): Q, K projections and attention output.
__device__ float g_Q[(size_t)MTOT * EDIM];
__device__ float g_K[(size_t)MTOT * EDIM];
__device__ float g_O[(size_t)MTOT * EDIM];

// ---------------------------------------------------------------------------
// tf32 helpers
// ---------------------------------------------------------------------------
__device__ __forceinline__ uint32_t tf32_cvt(float x)
{
    uint32_t h;
    asm("cvt.rna.tf32.f32 %0, %1;" : "=r"(h) : "f"(x));
    return h;
}

__device__ __forceinline__ void mma_tf32(float* d, const uint32_t* a, const uint32_t* b)
{
    asm volatile(
        "mma.sync.aligned.m16n8k8.row.col.f32.tf32.tf32.f32 "
        "{%0,%1,%2,%3}, {%4,%5,%6,%7}, {%8,%9}, {%0,%1,%2,%3};\n"
        : "+f"(d[0]), "+f"(d[1]), "+f"(d[2]), "+f"(d[3])
        : "r"(a[0]), "r"(a[1]), "r"(a[2]), "r"(a[3]),
          "r"(b[0]), "r"(b[1]));
}

// ---------------------------------------------------------------------------
// GEMM (NT) via single tf32 tensor cores:
// C[m][n] = sum_k A[m][k] * W[n][k] + bias[n]
// CTA 128x128, BK=32, 8 warps (2m x 4n), warp tile 64x32.
// tf32 conversion happens ONCE at smem-store; inner loop is pure LDS + MMA.
// ---------------------------------------------------------------------------
#define BM 128
#define BN 128
#define BK 32
#define SP 36   // smem pitch: (36*row + k) % 32 == (4*row + k) % 32 -> conflict-free frags

__global__ __launch_bounds__(256, 2) void gemm_tf32_bias(
    const float* __restrict__ A, const float* __restrict__ W,
    const float* __restrict__ bias, float* __restrict__ C,
    int M, int N, int K)
{
    __shared__ uint32_t As[BM][SP];   // tf32(A)[m][k]
    __shared__ uint32_t Ws[BN][SP];   // tf32(W)[n][k]

    const int tid  = threadIdx.x;
    const int warp = tid >> 5;
    const int lane = tid & 31;
    const int g    = lane >> 2;   // groupID 0..7
    const int t    = lane & 3;    // threadInGroup 0..3

    const int wm = (warp & 1) * 64;   // warp m-offset in tile
    const int wn = (warp >> 1) * 32;  // warp n-offset in tile

    const int m0 = blockIdx.y * BM;
    const int n0 = blockIdx.x * BN;

    // gmem load mapping: 8 threads per 32-float row
    const int lr = tid >> 3;         // 0..31 row within 32-row group
    const int lc = (tid & 7) * 4;    // float4 col within 32-float k slab

    float acc[4][4][4];
#pragma unroll
    for (int i = 0; i < 4; i++)
#pragma unroll
        for (int j = 0; j < 4; j++)
#pragma unroll
            for (int c = 0; c < 4; c++) acc[i][j][c] = 0.0f;

    for (int k0 = 0; k0 < K; k0 += BK) {
        float4 av[4], wv[4];
#pragma unroll
        for (int i = 0; i < 4; i++) {
            av[i] = *reinterpret_cast<const float4*>(
                &A[(size_t)(m0 + lr + i * 32) * K + k0 + lc]);
            wv[i] = *reinterpret_cast<const float4*>(
                &W[(size_t)(n0 + lr + i * 32) * K + k0 + lc]);
        }
        __syncthreads();
#pragma unroll
        for (int i = 0; i < 4; i++) {
            *reinterpret_cast<uint4*>(&As[lr + i * 32][lc]) =
                make_uint4(tf32_cvt(av[i].x), tf32_cvt(av[i].y),
                           tf32_cvt(av[i].z), tf32_cvt(av[i].w));
            *reinterpret_cast<uint4*>(&Ws[lr + i * 32][lc]) =
                make_uint4(tf32_cvt(wv[i].x), tf32_cvt(wv[i].y),
                           tf32_cvt(wv[i].z), tf32_cvt(wv[i].w));
        }
        __syncthreads();

#pragma unroll
        for (int kk = 0; kk < BK; kk += 8) {
            uint32_t a[4][4], b[4][2];
#pragma unroll
            for (int mt = 0; mt < 4; mt++) {
                const int r0 = wm + mt * 16 + g;
                a[mt][0] = As[r0    ][kk + t    ];
                a[mt][1] = As[r0 + 8][kk + t    ];
                a[mt][2] = As[r0    ][kk + t + 4];
                a[mt][3] = As[r0 + 8][kk + t + 4];
            }
#pragma unroll
            for (int nt = 0; nt < 4; nt++) {
                const int c0 = wn + nt * 8 + g;
                b[nt][0] = Ws[c0][kk + t    ];
                b[nt][1] = Ws[c0][kk + t + 4];
            }
#pragma unroll
            for (int mt = 0; mt < 4; mt++)
#pragma unroll
                for (int nt = 0; nt < 4; nt++)
                    mma_tf32(acc[mt][nt], a[mt], b[nt]);
        }
    }

    // Epilogue: c0=(g,2t) c1=(g,2t+1) c2=(g+8,2t) c3=(g+8,2t+1)
#pragma unroll
    for (int nt = 0; nt < 4; nt++) {
        const int n = n0 + wn + nt * 8 + 2 * t;
        const float2 bv = *reinterpret_cast<const float2*>(&bias[n]);
#pragma unroll
        for (int mt = 0; mt < 4; mt++) {
            const size_t r0 = (size_t)(m0 + wm + mt * 16 + g);
            const size_t r1 = r0 + 8;
            float2 o0 = make_float2(acc[mt][nt][0] + bv.x, acc[mt][nt][1] + bv.y);
            float2 o1 = make_float2(acc[mt][nt][2] + bv.x, acc[mt][nt][3] + bv.y);
            *reinterpret_cast<float2*>(&C[r0 * N + n]) = o0;
            *reinterpret_cast<float2*>(&C[r1 * N + n]) = o1;
        }
    }
}

// ---------------------------------------------------------------------------
// Flash attention via mma.sync tf32 (single precision tf32 everywhere).
// One CTA per (128 queries, head, batch). 8 warps x 16 query rows. V == K.
// All smem operands stored pre-converted to tf32.
// ---------------------------------------------------------------------------
#define PIT 68   // smem pitch (words): 68 % 32 == 4 -> (4g + t) patterns conflict-free
#define ATTN_SMEM_WORDS (2 * 128 * PIT + 64 * PIT)
#define ATTN_SMEM_BYTES (ATTN_SMEM_WORDS * 4)

__global__ __launch_bounds__(256, 2) void attn_mma(
    const float* __restrict__ Q, const float* __restrict__ K,
    float* __restrict__ O)
{
    extern __shared__ uint32_t smu[];
    uint32_t* Qt = smu;                 // [128][PIT] tf32(prescaled Q), [q][d]
    uint32_t* Pt = Qt + 128 * PIT;      // [128][PIT] tf32(P), [q][key]
    uint32_t* Kh = Pt + 128 * PIT;      // [64][PIT]  tf32(K), [key][d]

    const int tid  = threadIdx.x;
    const int warp = tid >> 5;
    const int lane = tid & 31;
    const int g = lane >> 2, t = lane & 3;
    const int wq = warp * 16;           // warp's query-row base

    const int qt = blockIdx.x, h = blockIdx.y, b = blockIdx.z;
    const int q0 = qt * 128;

    // Load Q tile (prescaled by 1/8), convert to tf32, natural [q][d] layout.
    {
        const int r  = tid >> 1;
        const int dc = (tid & 1) * 32;
        const float* src = &Q[((size_t)(b * SEQ + q0 + r)) * EDIM + h * HD + dc];
        uint32_t* dst = &Qt[r * PIT + dc];
#pragma unroll
        for (int c = 0; c < 8; c++) {
            float4 v = *reinterpret_cast<const float4*>(src + c * 4);
            *reinterpret_cast<uint4*>(dst + c * 4) =
                make_uint4(tf32_cvt(v.x * 0.125f), tf32_cvt(v.y * 0.125f),
                           tf32_cvt(v.z * 0.125f), tf32_cvt(v.w * 0.125f));
        }
    }

    float o[8][4];
#pragma unroll
    for (int i = 0; i < 8; i++)
#pragma unroll
        for (int j = 0; j < 4; j++) o[i][j] = 0.0f;
    float m0 = -1e30f, m1 = -1e30f, l0 = 0.0f, l1 = 0.0f;

    const int kr = tid >> 2;        // 0..63 key row
    const int kd = (tid & 3) << 4;  // 0,16,32,48 d-chunk base

    for (int kt = 0; kt < SEQ / 64; kt++) {
        // Stage next K tile (gmem loads issued before the barrier).
        float4 kv[4];
        const float* krow = &K[((size_t)(b * SEQ + kt * 64 + kr)) * EDIM + h * HD + kd];
#pragma unroll
        for (int c = 0; c < 4; c++)
            kv[c] = *reinterpret_cast<const float4*>(krow + c * 4);

        __syncthreads();  // all warps done reading Kh (and Qt store visible, iter 0)
#pragma unroll
        for (int c = 0; c < 4; c++)
            *reinterpret_cast<uint4*>(&Kh[kr * PIT + kd + c * 4]) =
                make_uint4(tf32_cvt(kv[c].x), tf32_cvt(kv[c].y),
                           tf32_cvt(kv[c].z), tf32_cvt(kv[c].w));
        __syncthreads();

        // ---- S = (Q*scale) K^T ----
        float s[8][4];
#pragma unroll
        for (int i = 0; i < 8; i++)
#pragma unroll
            for (int j = 0; j < 4; j++) s[i][j] = 0.0f;

#pragma unroll
        for (int kk = 0; kk < 8; kk++) {
            const int ak = kk * 8 + t;   // d index
            uint32_t a[4];
            a[0] = Qt[(wq + g    ) * PIT + ak    ];
            a[1] = Qt[(wq + g + 8) * PIT + ak    ];
            a[2] = Qt[(wq + g    ) * PIT + ak + 4];
            a[3] = Qt[(wq + g + 8) * PIT + ak + 4];
#pragma unroll
            for (int nt = 0; nt < 8; nt++) {
                uint32_t bb[2];
                bb[0] = Kh[(nt * 8 + g) * PIT + ak    ];
                bb[1] = Kh[(nt * 8 + g) * PIT + ak + 4];
                mma_tf32(s[nt], a, bb);
            }
        }

        // ---- online softmax (rows g and g+8 of warp tile; quad holds a row) ----
        float rmax0 = -1e30f, rmax1 = -1e30f;
#pragma unroll
        for (int nt = 0; nt < 8; nt++) {
            rmax0 = fmaxf(rmax0, fmaxf(s[nt][0], s[nt][1]));
            rmax1 = fmaxf(rmax1, fmaxf(s[nt][2], s[nt][3]));
        }
#pragma unroll
        for (int off = 1; off <= 2; off <<= 1) {
            rmax0 = fmaxf(rmax0, __shfl_xor_sync(0xffffffffu, rmax0, off));
            rmax1 = fmaxf(rmax1, __shfl_xor_sync(0xffffffffu, rmax1, off));
        }
        const float mn0 = fmaxf(m0, rmax0);
        const float mn1 = fmaxf(m1, rmax1);
        const float al0 = __expf(m0 - mn0);
        const float al1 = __expf(m1 - mn1);
        m0 = mn0; m1 = mn1;

        float sum0 = 0.0f, sum1 = 0.0f;
#pragma unroll
        for (int nt = 0; nt < 8; nt++) {
            s[nt][0] = __expf(s[nt][0] - mn0);
            s[nt][1] = __expf(s[nt][1] - mn0);
            s[nt][2] = __expf(s[nt][2] - mn1);
            s[nt][3] = __expf(s[nt][3] - mn1);
            sum0 += s[nt][0] + s[nt][1];
            sum1 += s[nt][2] + s[nt][3];
        }
#pragma unroll
        for (int off = 1; off <= 2; off <<= 1) {
            sum0 += __shfl_xor_sync(0xffffffffu, sum0, off);
            sum1 += __shfl_xor_sync(0xffffffffu, sum1, off);
        }
        l0 = l0 * al0 + sum0;
        l1 = l1 * al1 + sum1;
#pragma unroll
        for (int nd = 0; nd < 8; nd++) {
            o[nd][0] *= al0; o[nd][1] *= al0;
            o[nd][2] *= al1; o[nd][3] *= al1;
        }

        // ---- stage P to smem as tf32, [q][key] (own warp's 16 rows only) ----
#pragma unroll
        for (int nt = 0; nt < 8; nt++) {
            *reinterpret_cast<uint2*>(&Pt[(wq + g    ) * PIT + nt * 8 + 2 * t]) =
                make_uint2(tf32_cvt(s[nt][0]), tf32_cvt(s[nt][1]));
            *reinterpret_cast<uint2*>(&Pt[(wq + g + 8) * PIT + nt * 8 + 2 * t]) =
                make_uint2(tf32_cvt(s[nt][2]), tf32_cvt(s[nt][3]));
        }
        __syncwarp();

        // ---- O += P @ V (V = K tile) ----
#pragma unroll
        for (int kk = 0; kk < 8; kk++) {
            const int pk = kk * 8 + t;   // key index
            uint32_t pa[4];
            pa[0] = Pt[(wq + g    ) * PIT + pk    ];
            pa[1] = Pt[(wq + g + 8) * PIT + pk    ];
            pa[2] = Pt[(wq + g    ) * PIT + pk + 4];
            pa[3] = Pt[(wq + g + 8) * PIT + pk + 4];
#pragma unroll
            for (int nd = 0; nd < 8; nd++) {
                uint32_t bb[2];
                bb[0] = Kh[(pk    ) * PIT + nd * 8 + g];
                bb[1] = Kh[(pk + 4) * PIT + nd * 8 + g];
                mma_tf32(o[nd], pa, bb);
            }
        }
    }

    // ---- normalize and write [B,S,E] ----
    const float inv0 = 1.0f / l0;
    const float inv1 = 1.0f / l1;
    const size_t row0 = (size_t)(b * SEQ + q0 + wq + g) * EDIM + h * HD;
    const size_t row1 = row0 + (size_t)8 * EDIM;
#pragma unroll
    for (int nd = 0; nd < 8; nd++) {
        const int col = nd * 8 + 2 * t;
        *reinterpret_cast<float2*>(&O[row0 + col]) =
            make_float2(o[nd][0] * inv0, o[nd][1] * inv0);
        *reinterpret_cast<float2*>(&O[row1 + col]) =
            make_float2(o[nd][2] * inv1, o[nd][3] * inv1);
    }
}

// ---------------------------------------------------------------------------
extern "C" void kernel_launch(void* const* d_in, const int* in_sizes, int n_in,
                              void* d_out, int out_size)
{
    const float* x  = (const float*)d_in[0];
    const float* Wq = (const float*)d_in[1];
    const float* bq = (const float*)d_in[2];
    const float* Wk = (const float*)d_in[3];
    const float* bk = (const float*)d_in[4];
    const float* Wo = (const float*)d_in[5];
    const float* bo = (const float*)d_in[6];
    float* out = (float*)d_out;

    float *Qb, *Kb, *Ob;
    cudaGetSymbolAddress((void**)&Qb, g_Q);
    cudaGetSymbolAddress((void**)&Kb, g_K);
    cudaGetSymbolAddress((void**)&Ob, g_O);

    cudaFuncSetAttribute(attn_mma,
                         cudaFuncAttributeMaxDynamicSharedMemorySize,
                         ATTN_SMEM_BYTES);

    dim3 gblk(256);
    dim3 ggrid(EDIM / BN, MTOT / BM);   // (6, 64)

    // Q and K projections
    gemm_tf32_bias<<<ggrid, gblk>>>(x, Wq, bq, Qb, MTOT, EDIM, EDIM);
    gemm_tf32_bias<<<ggrid, gblk>>>(x, Wk, bk, Kb, MTOT, EDIM, EDIM);

    // Attention (V aliases K per the reference)
    dim3 agrid(SEQ / 128, NH, BATCH);   // (8, 12, 8)
    attn_mma<<<agrid, 256, ATTN_SMEM_BYTES>>>(Qb, Kb, Ob);

    // Output projection
    gemm_tf32_bias<<<ggrid, gblk>>>(Ob, Wo, bo, out, MTOT, EDIM, EDIM);
}

// round 7
// speedup vs baseline: 2.9200x; 1.0297x over previous
#include <cuda_runtime.h>
#include <cstddef>
#include <cstdint>

#define EDIM   768
#define BATCH  8
#define SEQ    1024
#define NH     12
#define HD     64
#define MTOT   (BATCH * SEQ)   // 8192

// Scratch (no cudaMalloc allowed).
__device__ float g_Q [(size_t)MTOT * EDIM];
__device__ float g_K [(size_t)MTOT * EDIM];
__device__ float g_O [(size_t)MTOT * EDIM];
__device__ float g_X [(size_t)MTOT * EDIM];   // tf32-rounded x
__device__ float g_Wq[(size_t)EDIM * EDIM];   // tf32-rounded weights
__device__ float g_Wk[(size_t)EDIM * EDIM];
__device__ float g_Wo[(size_t)EDIM * EDIM];

// ---------------------------------------------------------------------------
// helpers
// ---------------------------------------------------------------------------
__device__ __forceinline__ uint32_t tf32_cvt(float x)
{
    uint32_t h;
    asm("cvt.rna.tf32.f32 %0, %1;" : "=r"(h) : "f"(x));
    return h;
}

__device__ __forceinline__ void mma_tf32(float* d, const uint32_t* a, const uint32_t* b)
{
    asm volatile(
        "mma.sync.aligned.m16n8k8.row.col.f32.tf32.tf32.f32 "
        "{%0,%1,%2,%3}, {%4,%5,%6,%7}, {%8,%9}, {%0,%1,%2,%3};\n"
        : "+f"(d[0]), "+f"(d[1]), "+f"(d[2]), "+f"(d[3])
        : "r"(a[0]), "r"(a[1]), "r"(a[2]), "r"(a[3]),
          "r"(b[0]), "r"(b[1]));
}

__device__ __forceinline__ uint32_t sptr(const void* p)
{
    return (uint32_t)__cvta_generic_to_shared(p);
}

__device__ __forceinline__ void cp16(uint32_t s, const void* g)
{
    asm volatile("cp.async.cg.shared.global [%0], [%1], 16;\n" :: "r"(s), "l"(g));
}

// Elementwise tf32 rounding (idempotent): out[i] = round_tf32(in[i])
__global__ void round_tf32_kernel(const float* __restrict__ in,
                                  float* __restrict__ out, int n4)
{
    int i = blockIdx.x * blockDim.x + threadIdx.x;
    if (i < n4) {
        float4 v = reinterpret_cast<const float4*>(in)[i];
        float4 r;
        r.x = __uint_as_float(tf32_cvt(v.x));
        r.y = __uint_as_float(tf32_cvt(v.y));
        r.z = __uint_as_float(tf32_cvt(v.z));
        r.w = __uint_as_float(tf32_cvt(v.w));
        reinterpret_cast<float4*>(out)[i] = r;
    }
}

// ---------------------------------------------------------------------------
// GEMM (NT), inputs pre-rounded to tf32. 2-stage cp.async pipeline.
// C[m][n] = sum_k A[m][k]*W[n][k] + bias[n]. CTA 128x128, BK=32, 8 warps.
// round_out: round C to tf32 (for tensors feeding later tf32 MMAs).
// ---------------------------------------------------------------------------
#define BM 128
#define BN 128
#define BK 32
#define SP 36                       // pitch: (36r + k) % 32 = (4r + k) -> conflict-free
#define STG_FLOATS (2 * BM * SP)    // As + Ws per stage
#define GEMM_SMEM_BYTES (2 * STG_FLOATS * 4)

__device__ __forceinline__ void gemm_load_stage(
    float* stg, const float* A, const float* W,
    int m0, int n0, int k0, int K, int lr, int lc)
{
    float* as = stg;
    float* ws = stg + BM * SP;
#pragma unroll
    for (int i = 0; i < 4; i++) {
        cp16(sptr(&as[(lr + i * 32) * SP + lc]), &A[(size_t)(m0 + lr + i * 32) * K + k0 + lc]);
        cp16(sptr(&ws[(lr + i * 32) * SP + lc]), &W[(size_t)(n0 + lr + i * 32) * K + k0 + lc]);
    }
}

__global__ __launch_bounds__(256, 2) void gemm_tf32_bias(
    const float* __restrict__ A, const float* __restrict__ W,
    const float* __restrict__ bias, float* __restrict__ C,
    int M, int N, int K, int round_out)
{
    extern __shared__ float smg[];
    float* stg[2] = { smg, smg + STG_FLOATS };

    const int tid  = threadIdx.x;
    const int warp = tid >> 5;
    const int lane = tid & 31;
    const int g    = lane >> 2;
    const int t    = lane & 3;

    const int wm = (warp & 1) * 64;
    const int wn = (warp >> 1) * 32;
    const int m0 = blockIdx.y * BM;
    const int n0 = blockIdx.x * BN;

    const int lr = tid >> 3;         // 0..31
    const int lc = (tid & 7) * 4;    // 0..28

    float acc[4][4][4];
#pragma unroll
    for (int i = 0; i < 4; i++)
#pragma unroll
        for (int j = 0; j < 4; j++)
#pragma unroll
            for (int c = 0; c < 4; c++) acc[i][j][c] = 0.0f;

    const int NIT = K / BK;   // 24

    gemm_load_stage(stg[0], A, W, m0, n0, 0, K, lr, lc);
    asm volatile("cp.async.commit_group;\n");

    for (int it = 0; it < NIT; it++) {
        asm volatile("cp.async.wait_group 0;\n");
        __syncthreads();   // stage it&1 fully loaded; prev compute on other buf done

        if (it + 1 < NIT)
            gemm_load_stage(stg[(it + 1) & 1], A, W, m0, n0, (it + 1) * BK, K, lr, lc);
        asm volatile("cp.async.commit_group;\n");

        const uint32_t* As = reinterpret_cast<const uint32_t*>(stg[it & 1]);
        const uint32_t* Ws = As + BM * SP;

#pragma unroll
        for (int kk = 0; kk < BK; kk += 8) {
            uint32_t a[4][4], b[4][2];
#pragma unroll
            for (int mt = 0; mt < 4; mt++) {
                const int r0 = wm + mt * 16 + g;
                a[mt][0] = As[(r0    ) * SP + kk + t    ];
                a[mt][1] = As[(r0 + 8) * SP + kk + t    ];
                a[mt][2] = As[(r0    ) * SP + kk + t + 4];
                a[mt][3] = As[(r0 + 8) * SP + kk + t + 4];
            }
#pragma unroll
            for (int nt = 0; nt < 4; nt++) {
                const int c0 = wn + nt * 8 + g;
                b[nt][0] = Ws[c0 * SP + kk + t    ];
                b[nt][1] = Ws[c0 * SP + kk + t + 4];
            }
#pragma unroll
            for (int mt = 0; mt < 4; mt++)
#pragma unroll
                for (int nt = 0; nt < 4; nt++)
                    mma_tf32(acc[mt][nt], a[mt], b[nt]);
        }
    }

    // Epilogue: c0=(g,2t) c1=(g,2t+1) c2=(g+8,2t) c3=(g+8,2t+1)
#pragma unroll
    for (int nt = 0; nt < 4; nt++) {
        const int n = n0 + wn + nt * 8 + 2 * t;
        const float2 bv = *reinterpret_cast<const float2*>(&bias[n]);
#pragma unroll
        for (int mt = 0; mt < 4; mt++) {
            const size_t r0 = (size_t)(m0 + wm + mt * 16 + g);
            const size_t r1 = r0 + 8;
            float v00 = acc[mt][nt][0] + bv.x, v01 = acc[mt][nt][1] + bv.y;
            float v10 = acc[mt][nt][2] + bv.x, v11 = acc[mt][nt][3] + bv.y;
            if (round_out) {
                v00 = __uint_as_float(tf32_cvt(v00));
                v01 = __uint_as_float(tf32_cvt(v01));
                v10 = __uint_as_float(tf32_cvt(v10));
                v11 = __uint_as_float(tf32_cvt(v11));
            }
            *reinterpret_cast<float2*>(&C[r0 * N + n]) = make_float2(v00, v01);
            *reinterpret_cast<float2*>(&C[r1 * N + n]) = make_float2(v10, v11);
        }
    }
}

// ---------------------------------------------------------------------------
// Flash attention via mma.sync tf32. Q/K arrive pre-rounded to tf32.
// One CTA per (128 queries, head, batch). 8 warps x 16 query rows. V == K.
// Next K-tile LDGs issue right after QK^T so latency hides under softmax+PV.
// Output rounded to tf32 (feeds GEMM3).
// ---------------------------------------------------------------------------
#define PIT 68
#define ATTN_SMEM_WORDS (2 * 128 * PIT + 64 * PIT)
#define ATTN_SMEM_BYTES (ATTN_SMEM_WORDS * 4)

__global__ __launch_bounds__(256, 2) void attn_mma(
    const float* __restrict__ Q, const float* __restrict__ K,
    float* __restrict__ O)
{
    extern __shared__ uint32_t smu[];
    uint32_t* Qt = smu;                 // [128][PIT] tf32 bits of Q*0.125, [q][d]
    uint32_t* Pt = Qt + 128 * PIT;      // [128][PIT] tf32 bits of P, [q][key]
    uint32_t* Kh = Pt + 128 * PIT;      // [64][PIT]  tf32 bits of K, [key][d]

    const int tid  = threadIdx.x;
    const int warp = tid >> 5;
    const int lane = tid & 31;
    const int g = lane >> 2, t = lane & 3;
    const int wq = warp * 16;

    const int qt = blockIdx.x, h = blockIdx.y, b = blockIdx.z;
    const int q0 = qt * 128;

    // Load Q tile; values already tf32-exact, x0.125 is exact (exp shift).
    {
        const int r  = tid >> 1;
        const int dc = (tid & 1) * 32;
        const float* src = &Q[((size_t)(b * SEQ + q0 + r)) * EDIM + h * HD + dc];
        uint32_t* dst = &Qt[r * PIT + dc];
#pragma unroll
        for (int c = 0; c < 8; c++) {
            float4 v = *reinterpret_cast<const float4*>(src + c * 4);
            *reinterpret_cast<uint4*>(dst + c * 4) =
                make_uint4(__float_as_uint(v.x * 0.125f), __float_as_uint(v.y * 0.125f),
                           __float_as_uint(v.z * 0.125f), __float_as_uint(v.w * 0.125f));
        }
    }

    float o[8][4];
#pragma unroll
    for (int i = 0; i < 8; i++)
#pragma unroll
        for (int j = 0; j < 4; j++) o[i][j] = 0.0f;
    float m0 = -1e30f, m1 = -1e30f, l0 = 0.0f, l1 = 0.0f;

    const int kr = tid >> 2;        // 0..63 key row
    const int kd = (tid & 3) << 4;  // 0,16,32,48 d-chunk base
    const float* kbase = &K[((size_t)(b * SEQ)) * EDIM + h * HD + kd];

    // Preload tile 0 into registers.
    float4 kv[4];
#pragma unroll
    for (int c = 0; c < 4; c++)
        kv[c] = *reinterpret_cast<const float4*>(kbase + (size_t)kr * EDIM + c * 4);

    for (int kt = 0; kt < SEQ / 64; kt++) {
        __syncthreads();  // prev PV done reading Kh; Qt store visible (iter 0)
#pragma unroll
        for (int c = 0; c < 4; c++)
            *reinterpret_cast<uint4*>(&Kh[kr * PIT + kd + c * 4]) =
                make_uint4(__float_as_uint(kv[c].x), __float_as_uint(kv[c].y),
                           __float_as_uint(kv[c].z), __float_as_uint(kv[c].w));
        __syncthreads();

        // ---- S = (Q*scale) K^T ----
        float s[8][4];
#pragma unroll
        for (int i = 0; i < 8; i++)
#pragma unroll
            for (int j = 0; j < 4; j++) s[i][j] = 0.0f;

#pragma unroll
        for (int kk = 0; kk < 8; kk++) {
            const int ak = kk * 8 + t;
            uint32_t a[4];
            a[0] = Qt[(wq + g    ) * PIT + ak    ];
            a[1] = Qt[(wq + g + 8) * PIT + ak    ];
            a[2] = Qt[(wq + g    ) * PIT + ak + 4];
            a[3] = Qt[(wq + g + 8) * PIT + ak + 4];
#pragma unroll
            for (int nt = 0; nt < 8; nt++) {
                uint32_t bb[2];
                bb[0] = Kh[(nt * 8 + g) * PIT + ak    ];
                bb[1] = Kh[(nt * 8 + g) * PIT + ak + 4];
                mma_tf32(s[nt], a, bb);
            }
        }

        // Prefetch next K tile NOW; latency hides under softmax + PV.
        if (kt + 1 < SEQ / 64) {
            const float* krow = kbase + (size_t)((kt + 1) * 64 + kr) * EDIM;
#pragma unroll
            for (int c = 0; c < 4; c++)
                kv[c] = *reinterpret_cast<const float4*>(krow + c * 4);
        }

        // ---- online softmax ----
        float rmax0 = -1e30f, rmax1 = -1e30f;
#pragma unroll
        for (int nt = 0; nt < 8; nt++) {
            rmax0 = fmaxf(rmax0, fmaxf(s[nt][0], s[nt][1]));
            rmax1 = fmaxf(rmax1, fmaxf(s[nt][2], s[nt][3]));
        }
#pragma unroll
        for (int off = 1; off <= 2; off <<= 1) {
            rmax0 = fmaxf(rmax0, __shfl_xor_sync(0xffffffffu, rmax0, off));
            rmax1 = fmaxf(rmax1, __shfl_xor_sync(0xffffffffu, rmax1, off));
        }
        const float mn0 = fmaxf(m0, rmax0);
        const float mn1 = fmaxf(m1, rmax1);
        const float al0 = __expf(m0 - mn0);
        const float al1 = __expf(m1 - mn1);
        m0 = mn0; m1 = mn1;

        float sum0 = 0.0f, sum1 = 0.0f;
#pragma unroll
        for (int nt = 0; nt < 8; nt++) {
            s[nt][0] = __expf(s[nt][0] - mn0);
            s[nt][1] = __expf(s[nt][1] - mn0);
            s[nt][2] = __expf(s[nt][2] - mn1);
            s[nt][3] = __expf(s[nt][3] - mn1);
            sum0 += s[nt][0] + s[nt][1];
            sum1 += s[nt][2] + s[nt][3];
        }
#pragma unroll
        for (int off = 1; off <= 2; off <<= 1) {
            sum0 += __shfl_xor_sync(0xffffffffu, sum0, off);
            sum1 += __shfl_xor_sync(0xffffffffu, sum1, off);
        }
        l0 = l0 * al0 + sum0;
        l1 = l1 * al1 + sum1;
#pragma unroll
        for (int nd = 0; nd < 8; nd++) {
            o[nd][0] *= al0; o[nd][1] *= al0;
            o[nd][2] *= al1; o[nd][3] *= al1;
        }

        // ---- stage P (tf32) to smem [q][key], own warp's rows ----
#pragma unroll
        for (int nt = 0; nt < 8; nt++) {
            *reinterpret_cast<uint2*>(&Pt[(wq + g    ) * PIT + nt * 8 + 2 * t]) =
                make_uint2(tf32_cvt(s[nt][0]), tf32_cvt(s[nt][1]));
            *reinterpret_cast<uint2*>(&Pt[(wq + g + 8) * PIT + nt * 8 + 2 * t]) =
                make_uint2(tf32_cvt(s[nt][2]), tf32_cvt(s[nt][3]));
        }
        __syncwarp();

        // ---- O += P @ V (V = K tile) ----
#pragma unroll
        for (int kk = 0; kk < 8; kk++) {
            const int pk = kk * 8 + t;
            uint32_t pa[4];
            pa[0] = Pt[(wq + g    ) * PIT + pk    ];
            pa[1] = Pt[(wq + g + 8) * PIT + pk    ];
            pa[2] = Pt[(wq + g    ) * PIT + pk + 4];
            pa[3] = Pt[(wq + g + 8) * PIT + pk + 4];
#pragma unroll
            for (int nd = 0; nd < 8; nd++) {
                uint32_t bb[2];
                bb[0] = Kh[(pk    ) * PIT + nd * 8 + g];
                bb[1] = Kh[(pk + 4) * PIT + nd * 8 + g];
                mma_tf32(o[nd], pa, bb);
            }
        }
    }

    // ---- normalize, round to tf32 (feeds GEMM3), write [B,S,E] ----
    const float inv0 = 1.0f / l0;
    const float inv1 = 1.0f / l1;
    const size_t row0 = (size_t)(b * SEQ + q0 + wq + g) * EDIM + h * HD;
    const size_t row1 = row0 + (size_t)8 * EDIM;
#pragma unroll
    for (int nd = 0; nd < 8; nd++) {
        const int col = nd * 8 + 2 * t;
        *reinterpret_cast<uint2*>(&O[row0 + col]) =
            make_uint2(tf32_cvt(o[nd][0] * inv0), tf32_cvt(o[nd][1] * inv0));
        *reinterpret_cast<uint2*>(&O[row1 + col]) =
            make_uint2(tf32_cvt(o[nd][2] * inv1), tf32_cvt(o[nd][3] * inv1));
    }
}

// ---------------------------------------------------------------------------
extern "C" void kernel_launch(void* const* d_in, const int* in_sizes, int n_in,
                              void* d_out, int out_size)
{
    const float* x  = (const float*)d_in[0];
    const float* Wq = (const float*)d_in[1];
    const float* bq = (const float*)d_in[2];
    const float* Wk = (const float*)d_in[3];
    const float* bk = (const float*)d_in[4];
    const float* Wo = (const float*)d_in[5];
    const float* bo = (const float*)d_in[6];
    float* out = (float*)d_out;

    float *Qb, *Kb, *Ob, *Xb, *Wqb, *Wkb, *Wob;
    cudaGetSymbolAddress((void**)&Qb,  g_Q);
    cudaGetSymbolAddress((void**)&Kb,  g_K);
    cudaGetSymbolAddress((void**)&Ob,  g_O);
    cudaGetSymbolAddress((void**)&Xb,  g_X);
    cudaGetSymbolAddress((void**)&Wqb, g_Wq);
    cudaGetSymbolAddress((void**)&Wkb, g_Wk);
    cudaGetSymbolAddress((void**)&Wob, g_Wo);

    cudaFuncSetAttribute(gemm_tf32_bias,
                         cudaFuncAttributeMaxDynamicSharedMemorySize,
                         GEMM_SMEM_BYTES);
    cudaFuncSetAttribute(attn_mma,
                         cudaFuncAttributeMaxDynamicSharedMemorySize,
                         ATTN_SMEM_BYTES);

    // Pre-round inputs to tf32 (idempotent; removes all cvts from GEMMs).
    {
        const int nx4 = MTOT * EDIM / 4;
        const int nw4 = EDIM * EDIM / 4;
        round_tf32_kernel<<<(nx4 + 255) / 256, 256>>>(x,  Xb,  nx4);
        round_tf32_kernel<<<(nw4 + 255) / 256, 256>>>(Wq, Wqb, nw4);
        round_tf32_kernel<<<(nw4 + 255) / 256, 256>>>(Wk, Wkb, nw4);
        round_tf32_kernel<<<(nw4 + 255) / 256, 256>>>(Wo, Wob, nw4);
    }

    dim3 gblk(256);
    dim3 ggrid(EDIM / BN, MTOT / BM);   // (6, 64)

    // Q and K projections (outputs rounded to tf32 for attention)
    gemm_tf32_bias<<<ggrid, gblk, GEMM_SMEM_BYTES>>>(Xb, Wqb, bq, Qb, MTOT, EDIM, EDIM, 1);
    gemm_tf32_bias<<<ggrid, gblk, GEMM_SMEM_BYTES>>>(Xb, Wkb, bk, Kb, MTOT, EDIM, EDIM, 1);

    // Attention (V aliases K per the reference)
    dim3 agrid(SEQ / 128, NH, BATCH);   // (8, 12, 8)
    attn_mma<<<agrid, 256, ATTN_SMEM_BYTES>>>(Qb, Kb, Ob);

    // Output projection (fp32 output)
    gemm_tf32_bias<<<ggrid, gblk, GEMM_SMEM_BYTES>>>(Ob, Wob, bo, out, MTOT, EDIM, EDIM, 0);
}

// round 8
// speedup vs baseline: 3.4572x; 1.1840x over previous
#include <cuda_runtime.h>
#include <cstddef>
#include <cstdint>

#define EDIM   768
#define BATCH  8
#define SEQ    1024
#define NH     12
#define HD     64
#define MTOT   (BATCH * SEQ)   // 8192

// Scratch (no cudaMalloc allowed).
__device__ float g_Q [(size_t)MTOT * EDIM];
__device__ float g_K [(size_t)MTOT * EDIM];
__device__ float g_O [(size_t)MTOT * EDIM];
__device__ float g_X [(size_t)MTOT * EDIM];   // tf32-rounded x
__device__ float g_Wq[(size_t)EDIM * EDIM];   // tf32-rounded weights
__device__ float g_Wk[(size_t)EDIM * EDIM];
__device__ float g_Wo[(size_t)EDIM * EDIM];

// ---------------------------------------------------------------------------
// helpers
// ---------------------------------------------------------------------------
__device__ __forceinline__ uint32_t tf32_cvt(float x)
{
    uint32_t h;
    asm("cvt.rna.tf32.f32 %0, %1;" : "=r"(h) : "f"(x));
    return h;
}

__device__ __forceinline__ void mma_tf32(float* d, const uint32_t* a, const uint32_t* b)
{
    asm volatile(
        "mma.sync.aligned.m16n8k8.row.col.f32.tf32.tf32.f32 "
        "{%0,%1,%2,%3}, {%4,%5,%6,%7}, {%8,%9}, {%0,%1,%2,%3};\n"
        : "+f"(d[0]), "+f"(d[1]), "+f"(d[2]), "+f"(d[3])
        : "r"(a[0]), "r"(a[1]), "r"(a[2]), "r"(a[3]),
          "r"(b[0]), "r"(b[1]));
}

// ldmatrix x4 on b16: four 8x8-b16 tiles == four (8 rows x 4 tf32-col) tiles.
// Lane l supplies the 16B row address of tile (l>>3), row (l&7).
// Result reg i holds tile i's word for (row = lane>>2, tf32col = lane&3).
__device__ __forceinline__ void ldsm4(uint32_t* r, uint32_t saddr)
{
    asm volatile(
        "ldmatrix.sync.aligned.m8n8.x4.shared.b16 {%0,%1,%2,%3}, [%4];\n"
        : "=r"(r[0]), "=r"(r[1]), "=r"(r[2]), "=r"(r[3]) : "r"(saddr));
}

__device__ __forceinline__ uint32_t sptr(const void* p)
{
    return (uint32_t)__cvta_generic_to_shared(p);
}

__device__ __forceinline__ void cp16(uint32_t s, const void* g)
{
    asm volatile("cp.async.cg.shared.global [%0], [%1], 16;\n" :: "r"(s), "l"(g));
}

// Combined elementwise tf32 rounding for x, Wq, Wk, Wo in one launch.
__global__ void round_all_kernel(
    const float* __restrict__ x,  const float* __restrict__ wq,
    const float* __restrict__ wk, const float* __restrict__ wo,
    float* __restrict__ xo, float* __restrict__ wqo,
    float* __restrict__ wko, float* __restrict__ woo)
{
    const int NX4 = MTOT * EDIM / 4;
    const int NW4 = EDIM * EDIM / 4;
    int i = blockIdx.x * blockDim.x + threadIdx.x;
    const float4* src; float4* dst; int j;
    if (i < NX4)                { src = (const float4*)x;  dst = (float4*)xo;  j = i; }
    else if (i < NX4 + NW4)     { src = (const float4*)wq; dst = (float4*)wqo; j = i - NX4; }
    else if (i < NX4 + 2 * NW4) { src = (const float4*)wk; dst = (float4*)wko; j = i - NX4 - NW4; }
    else if (i < NX4 + 3 * NW4) { src = (const float4*)wo; dst = (float4*)woo; j = i - NX4 - 2 * NW4; }
    else return;
    float4 v = src[j];
    float4 r;
    r.x = __uint_as_float(tf32_cvt(v.x));
    r.y = __uint_as_float(tf32_cvt(v.y));
    r.z = __uint_as_float(tf32_cvt(v.z));
    r.w = __uint_as_float(tf32_cvt(v.w));
    dst[j] = r;
}

// ---------------------------------------------------------------------------
// GEMM (NT), inputs pre-rounded tf32. cp.async 2-stage + LDSM fragments.
// C[m][n] = sum_k A[m][k]*W[n][k] + bias[n]. CTA 128x128, BK=32, 8 warps.
// ---------------------------------------------------------------------------
#define BM 128
#define BN 128
#define BK 32
#define SP 36                       // pitch: (4r + k) mod 32 -> conflict-free rows
#define STG_FLOATS (2 * BM * SP)
#define GEMM_SMEM_BYTES (2 * STG_FLOATS * 4)

__device__ __forceinline__ void gemm_load_stage(
    float* stg, const float* A, const float* W,
    int m0, int n0, int k0, int K, int lr, int lc)
{
    float* as = stg;
    float* ws = stg + BM * SP;
#pragma unroll
    for (int i = 0; i < 4; i++) {
        cp16(sptr(&as[(lr + i * 32) * SP + lc]), &A[(size_t)(m0 + lr + i * 32) * K + k0 + lc]);
        cp16(sptr(&ws[(lr + i * 32) * SP + lc]), &W[(size_t)(n0 + lr + i * 32) * K + k0 + lc]);
    }
}

__global__ __launch_bounds__(256, 2) void gemm_tf32_bias(
    const float* __restrict__ A, const float* __restrict__ W,
    const float* __restrict__ bias, float* __restrict__ C,
    int M, int N, int K, int round_out)
{
    extern __shared__ float smg[];
    float* stg[2] = { smg, smg + STG_FLOATS };

    const int tid  = threadIdx.x;
    const int warp = tid >> 5;
    const int lane = tid & 31;
    const int g    = lane >> 2;
    const int t    = lane & 3;

    const int wm = (warp & 1) * 64;
    const int wn = (warp >> 1) * 32;
    const int m0 = blockIdx.y * BM;
    const int n0 = blockIdx.x * BN;

    const int lr = tid >> 3;         // 0..31
    const int lc = (tid & 7) * 4;    // 0..28

    // LDSM per-lane byte addresses (stage 0); add stage/chunk offsets later.
    // A tiles: {rows+0,col+0},{rows+8,col+0},{rows+0,col+4},{rows+8,col+4}
    uint32_t aab[4], bab[2];
    {
        const uint32_t base = sptr(smg);
        const int arow = ((lane >> 3) & 1) * 8 + (lane & 7);
        const int acol = ((lane >> 4) & 1) * 4;
#pragma unroll
        for (int mt = 0; mt < 4; mt++)
            aab[mt] = base + (uint32_t)(((wm + mt * 16 + arow) * SP + acol) * 4);
        // B tiles for nt-pair j: {nt0rows,c0},{nt0rows,c4},{nt1rows,c0},{nt1rows,c4}
        const int brow = (lane >> 4) * 8 + (lane & 7);
        const int bcol = ((lane >> 3) & 1) * 4;
#pragma unroll
        for (int j = 0; j < 2; j++)
            bab[j] = base + (uint32_t)((BM * SP + (wn + j * 16 + brow) * SP + bcol) * 4);
    }
    const uint32_t stg_bytes = STG_FLOATS * 4;

    float acc[4][4][4];
#pragma unroll
    for (int i = 0; i < 4; i++)
#pragma unroll
        for (int j = 0; j < 4; j++)
#pragma unroll
            for (int c = 0; c < 4; c++) acc[i][j][c] = 0.0f;

    const int NIT = K / BK;   // 24

    gemm_load_stage(stg[0], A, W, m0, n0, 0, K, lr, lc);
    asm volatile("cp.async.commit_group;\n");

    for (int it = 0; it < NIT; it++) {
        asm volatile("cp.async.wait_group 0;\n");
        __syncthreads();

        if (it + 1 < NIT)
            gemm_load_stage(stg[(it + 1) & 1], A, W, m0, n0, (it + 1) * BK, K, lr, lc);
        asm volatile("cp.async.commit_group;\n");

        const uint32_t soff = (it & 1) * stg_bytes;

#pragma unroll
        for (int kc = 0; kc < 4; kc++) {          // 4 chunks of k8
            const uint32_t koff = soff + kc * 32; // 8 words
            uint32_t a[4][4], b[2][4];
#pragma unroll
            for (int mt = 0; mt < 4; mt++) ldsm4(a[mt], aab[mt] + koff);
#pragma unroll
            for (int j = 0; j < 2; j++)    ldsm4(b[j],  bab[j] + koff);
#pragma unroll
            for (int mt = 0; mt < 4; mt++)
#pragma unroll
                for (int j = 0; j < 2; j++) {
                    mma_tf32(acc[mt][2 * j    ], a[mt], &b[j][0]);
                    mma_tf32(acc[mt][2 * j + 1], a[mt], &b[j][2]);
                }
        }
    }

    // Epilogue: c0=(g,2t) c1=(g,2t+1) c2=(g+8,2t) c3=(g+8,2t+1)
#pragma unroll
    for (int nt = 0; nt < 4; nt++) {
        const int n = n0 + wn + nt * 8 + 2 * t;
        const float2 bv = *reinterpret_cast<const float2*>(&bias[n]);
#pragma unroll
        for (int mt = 0; mt < 4; mt++) {
            const size_t r0 = (size_t)(m0 + wm + mt * 16 + g);
            const size_t r1 = r0 + 8;
            float v00 = acc[mt][nt][0] + bv.x, v01 = acc[mt][nt][1] + bv.y;
            float v10 = acc[mt][nt][2] + bv.x, v11 = acc[mt][nt][3] + bv.y;
            if (round_out) {
                v00 = __uint_as_float(tf32_cvt(v00));
                v01 = __uint_as_float(tf32_cvt(v01));
                v10 = __uint_as_float(tf32_cvt(v10));
                v11 = __uint_as_float(tf32_cvt(v11));
            }
            *reinterpret_cast<float2*>(&C[r0 * N + n]) = make_float2(v00, v01);
            *reinterpret_cast<float2*>(&C[r1 * N + n]) = make_float2(v10, v11);
        }
    }
}

// ---------------------------------------------------------------------------
// Flash attention via mma.sync tf32 + LDSM fragments. Q/K pre-rounded tf32.
// One CTA per (128 queries, head, batch). 8 warps x 16 query rows. V == K.
// K kept in two layouts: Kh [key][d] (QK^T B-op), Kd [d][key] (PV B-op).
// ---------------------------------------------------------------------------
#define PIT 68
#define ATTN_SMEM_WORDS (2 * 128 * PIT + 2 * 64 * PIT)
#define ATTN_SMEM_BYTES (ATTN_SMEM_WORDS * 4)

__global__ __launch_bounds__(256, 2) void attn_mma(
    const float* __restrict__ Q, const float* __restrict__ K,
    float* __restrict__ O)
{
    extern __shared__ uint32_t smu[];
    uint32_t* Qt = smu;                 // [128][PIT] tf32 bits of Q*0.125, [q][d]
    uint32_t* Pt = Qt + 128 * PIT;      // [128][PIT] tf32 bits of P, [q][key]
    uint32_t* Kh = Pt + 128 * PIT;      // [64][PIT]  tf32 bits of K, [key][d]
    uint32_t* Kd = Kh + 64 * PIT;       // [64][PIT]  tf32 bits of K, [d][key]

    const int tid  = threadIdx.x;
    const int warp = tid >> 5;
    const int lane = tid & 31;
    const int g = lane >> 2, t = lane & 3;
    const int wq = warp * 16;

    const int qt = blockIdx.x, h = blockIdx.y, b = blockIdx.z;
    const int q0 = qt * 128;

    // Load Q tile; values tf32-exact, x0.125 exact (exponent shift).
    {
        const int r  = tid >> 1;
        const int dc = (tid & 1) * 32;
        const float* src = &Q[((size_t)(b * SEQ + q0 + r)) * EDIM + h * HD + dc];
        uint32_t* dst = &Qt[r * PIT + dc];
#pragma unroll
        for (int c = 0; c < 8; c++) {
            float4 v = *reinterpret_cast<const float4*>(src + c * 4);
            *reinterpret_cast<uint4*>(dst + c * 4) =
                make_uint4(__float_as_uint(v.x * 0.125f), __float_as_uint(v.y * 0.125f),
                           __float_as_uint(v.z * 0.125f), __float_as_uint(v.w * 0.125f));
        }
    }

    // LDSM per-lane byte addresses.
    const int frow = ((lane >> 3) & 1) * 8 + (lane & 7);  // A-tile row pattern
    const int fcol = ((lane >> 4) & 1) * 4;               // A-tile col pattern
    const int brow = (lane >> 4) * 8 + (lane & 7);        // B-pair row pattern
    const int bcol = ((lane >> 3) & 1) * 4;               // B-pair col pattern
    const uint32_t qa_base = sptr(Qt) + (uint32_t)(((wq + frow) * PIT + fcol) * 4);
    const uint32_t pa_base = sptr(Pt) + (uint32_t)(((wq + frow) * PIT + fcol) * 4);
    uint32_t kb_base[4], vb_base[4];
#pragma unroll
    for (int j = 0; j < 4; j++) {
        kb_base[j] = sptr(Kh) + (uint32_t)(((j * 16 + brow) * PIT + bcol) * 4);
        vb_base[j] = sptr(Kd) + (uint32_t)(((j * 16 + brow) * PIT + bcol) * 4);
    }

    float o[8][4];
#pragma unroll
    for (int i = 0; i < 8; i++)
#pragma unroll
        for (int j = 0; j < 4; j++) o[i][j] = 0.0f;
    float m0 = -1e30f, m1 = -1e30f, l0 = 0.0f, l1 = 0.0f;

    const int kr = tid >> 2;        // 0..63 key row
    const int kd = (tid & 3) << 4;  // 0,16,32,48 d-chunk base
    const float* kbase = &K[((size_t)(b * SEQ)) * EDIM + h * HD + kd];

    // Preload tile 0 into registers.
    float4 kv[4];
#pragma unroll
    for (int c = 0; c < 4; c++)
        kv[c] = *reinterpret_cast<const float4*>(kbase + (size_t)kr * EDIM + c * 4);

    for (int kt = 0; kt < SEQ / 64; kt++) {
        __syncthreads();  // prev PV done reading Kh/Kd; Qt store visible (iter 0)
#pragma unroll
        for (int c = 0; c < 4; c++) {
            // natural layout [key][d]
            *reinterpret_cast<uint4*>(&Kh[kr * PIT + kd + c * 4]) =
                make_uint4(__float_as_uint(kv[c].x), __float_as_uint(kv[c].y),
                           __float_as_uint(kv[c].z), __float_as_uint(kv[c].w));
            // transposed layout [d][key]
            const int db = kd + c * 4;
            Kd[(db + 0) * PIT + kr] = __float_as_uint(kv[c].x);
            Kd[(db + 1) * PIT + kr] = __float_as_uint(kv[c].y);
            Kd[(db + 2) * PIT + kr] = __float_as_uint(kv[c].z);
            Kd[(db + 3) * PIT + kr] = __float_as_uint(kv[c].w);
        }
        __syncthreads();

        // ---- S = (Q*scale) K^T ----
        float s[8][4];
#pragma unroll
        for (int i = 0; i < 8; i++)
#pragma unroll
            for (int j = 0; j < 4; j++) s[i][j] = 0.0f;

#pragma unroll
        for (int kc = 0; kc < 8; kc++) {
            const uint32_t koff = kc * 32;   // 8 d-words per chunk
            uint32_t a[4], bb[4][4];
            ldsm4(a, qa_base + koff);
#pragma unroll
            for (int j = 0; j < 4; j++) ldsm4(bb[j], kb_base[j] + koff);
#pragma unroll
            for (int j = 0; j < 4; j++) {
                mma_tf32(s[2 * j    ], a, &bb[j][0]);
                mma_tf32(s[2 * j + 1], a, &bb[j][2]);
            }
        }

        // Prefetch next K tile NOW; latency hides under softmax + PV.
        if (kt + 1 < SEQ / 64) {
            const float* krow = kbase + (size_t)((kt + 1) * 64 + kr) * EDIM;
#pragma unroll
            for (int c = 0; c < 4; c++)
                kv[c] = *reinterpret_cast<const float4*>(krow + c * 4);
        }

        // ---- online softmax ----
        float rmax0 = -1e30f, rmax1 = -1e30f;
#pragma unroll
        for (int nt = 0; nt < 8; nt++) {
            rmax0 = fmaxf(rmax0, fmaxf(s[nt][0], s[nt][1]));
            rmax1 = fmaxf(rmax1, fmaxf(s[nt][2], s[nt][3]));
        }
#pragma unroll
        for (int off = 1; off <= 2; off <<= 1) {
            rmax0 = fmaxf(rmax0, __shfl_xor_sync(0xffffffffu, rmax0, off));
            rmax1 = fmaxf(rmax1, __shfl_xor_sync(0xffffffffu, rmax1, off));
        }
        const float mn0 = fmaxf(m0, rmax0);
        const float mn1 = fmaxf(m1, rmax1);
        const float al0 = __expf(m0 - mn0);
        const float al1 = __expf(m1 - mn1);
        m0 = mn0; m1 = mn1;

        float sum0 = 0.0f, sum1 = 0.0f;
#pragma unroll
        for (int nt = 0; nt < 8; nt++) {
            s[nt][0] = __expf(s[nt][0] - mn0);
            s[nt][1] = __expf(s[nt][1] - mn0);
            s[nt][2] = __expf(s[nt][2] - mn1);
            s[nt][3] = __expf(s[nt][3] - mn1);
            sum0 += s[nt][0] + s[nt][1];
            sum1 += s[nt][2] + s[nt][3];
        }
#pragma unroll
        for (int off = 1; off <= 2; off <<= 1) {
            sum0 += __shfl_xor_sync(0xffffffffu, sum0, off);
            sum1 += __shfl_xor_sync(0xffffffffu, sum1, off);
        }
        l0 = l0 * al0 + sum0;
        l1 = l1 * al1 + sum1;
#pragma unroll
        for (int nd = 0; nd < 8; nd++) {
            o[nd][0] *= al0; o[nd][1] *= al0;
            o[nd][2] *= al1; o[nd][3] *= al1;
        }

        // ---- stage P (tf32) to smem [q][key], own warp's rows ----
#pragma unroll
        for (int nt = 0; nt < 8; nt++) {
            *reinterpret_cast<uint2*>(&Pt[(wq + g    ) * PIT + nt * 8 + 2 * t]) =
                make_uint2(tf32_cvt(s[nt][0]), tf32_cvt(s[nt][1]));
            *reinterpret_cast<uint2*>(&Pt[(wq + g + 8) * PIT + nt * 8 + 2 * t]) =
                make_uint2(tf32_cvt(s[nt][2]), tf32_cvt(s[nt][3]));
        }
        __syncwarp();

        // ---- O += P @ V (V = K tile; B-op from Kd [d][key]) ----
#pragma unroll
        for (int kc = 0; kc < 8; kc++) {
            const uint32_t koff = kc * 32;   // 8 key-words per chunk
            uint32_t a[4], bb[4][4];
            ldsm4(a, pa_base + koff);
#pragma unroll
            for (int j = 0; j < 4; j++) ldsm4(bb[j], vb_base[j] + koff);
#pragma unroll
            for (int j = 0; j < 4; j++) {
                mma_tf32(o[2 * j    ], a, &bb[j][0]);
                mma_tf32(o[2 * j + 1], a, &bb[j][2]);
            }
        }
    }

    // ---- normalize, round to tf32 (feeds GEMM3), write [B,S,E] ----
    const float inv0 = 1.0f / l0;
    const float inv1 = 1.0f / l1;
    const size_t row0 = (size_t)(b * SEQ + q0 + wq + g) * EDIM + h * HD;
    const size_t row1 = row0 + (size_t)8 * EDIM;
#pragma unroll
    for (int nd = 0; nd < 8; nd++) {
        const int col = nd * 8 + 2 * t;
        *reinterpret_cast<uint2*>(&O[row0 + col]) =
            make_uint2(tf32_cvt(o[nd][0] * inv0), tf32_cvt(o[nd][1] * inv0));
        *reinterpret_cast<uint2*>(&O[row1 + col]) =
            make_uint2(tf32_cvt(o[nd][2] * inv1), tf32_cvt(o[nd][3] * inv1));
    }
}

// ---------------------------------------------------------------------------
extern "C" void kernel_launch(void* const* d_in, const int* in_sizes, int n_in,
                              void* d_out, int out_size)
{
    const float* x  = (const float*)d_in[0];
    const float* Wq = (const float*)d_in[1];
    const float* bq = (const float*)d_in[2];
    const float* Wk = (const float*)d_in[3];
    const float* bk = (const float*)d_in[4];
    const float* Wo = (const float*)d_in[5];
    const float* bo = (const float*)d_in[6];
    float* out = (float*)d_out;

    float *Qb, *Kb, *Ob, *Xb, *Wqb, *Wkb, *Wob;
    cudaGetSymbolAddress((void**)&Qb,  g_Q);
    cudaGetSymbolAddress((void**)&Kb,  g_K);
    cudaGetSymbolAddress((void**)&Ob,  g_O);
    cudaGetSymbolAddress((void**)&Xb,  g_X);
    cudaGetSymbolAddress((void**)&Wqb, g_Wq);
    cudaGetSymbolAddress((void**)&Wkb, g_Wk);
    cudaGetSymbolAddress((void**)&Wob, g_Wo);

    cudaFuncSetAttribute(gemm_tf32_bias,
                         cudaFuncAttributeMaxDynamicSharedMemorySize,
                         GEMM_SMEM_BYTES);
    cudaFuncSetAttribute(attn_mma,
                         cudaFuncAttributeMaxDynamicSharedMemorySize,
                         ATTN_SMEM_BYTES);

    // Pre-round all GEMM inputs to tf32 in ONE launch (idempotent).
    {
        const int total = MTOT * EDIM / 4 + 3 * (EDIM * EDIM / 4);
        round_all_kernel<<<(total + 255) / 256, 256>>>(x, Wq, Wk, Wo,
                                                       Xb, Wqb, Wkb, Wob);
    }

    dim3 gblk(256);
    dim3 ggrid(EDIM / BN, MTOT / BM);   // (6, 64)

    // Q and K projections (outputs rounded to tf32 for attention)
    gemm_tf32_bias<<<ggrid, gblk, GEMM_SMEM_BYTES>>>(Xb, Wqb, bq, Qb, MTOT, EDIM, EDIM, 1);
    gemm_tf32_bias<<<ggrid, gblk, GEMM_SMEM_BYTES>>>(Xb, Wkb, bk, Kb, MTOT, EDIM, EDIM, 1);

    // Attention (V aliases K per the reference)
    dim3 agrid(SEQ / 128, NH, BATCH);   // (8, 12, 8)
    attn_mma<<<agrid, 256, ATTN_SMEM_BYTES>>>(Qb, Kb, Ob);

    // Output projection (fp32 output)
    gemm_tf32_bias<<<ggrid, gblk, GEMM_SMEM_BYTES>>>(Ob, Wob, bo, out, MTOT, EDIM, EDIM, 0);
}

// round 10
// speedup vs baseline: 4.3669x; 1.2631x over previous
#include <cuda_runtime.h>
#include <cuda_fp16.h>
#include <cstddef>
#include <cstdint>

#define EDIM   768
#define BATCH  8
#define SEQ    1024
#define NH     12
#define HD     64
#define MTOT   (BATCH * SEQ)   // 8192

// Scratch (no cudaMalloc allowed).
__device__ float g_Q [(size_t)MTOT * EDIM];
__device__ float g_K [(size_t)MTOT * EDIM];
__device__ float g_O [(size_t)MTOT * EDIM];
__device__ float g_X [(size_t)MTOT * EDIM];   // tf32-rounded x
__device__ float g_Wq[(size_t)EDIM * EDIM];   // tf32-rounded weights
__device__ float g_Wk[(size_t)EDIM * EDIM];
__device__ float g_Wo[(size_t)EDIM * EDIM];

// ---------------------------------------------------------------------------
// helpers
// ---------------------------------------------------------------------------
__device__ __forceinline__ uint32_t tf32_cvt(float x)
{
    uint32_t h;
    asm("cvt.rna.tf32.f32 %0, %1;" : "=r"(h) : "f"(x));
    return h;
}

__device__ __forceinline__ void mma_tf32(float* d, const uint32_t* a, const uint32_t* b)
{
    asm volatile(
        "mma.sync.aligned.m16n8k8.row.col.f32.tf32.tf32.f32 "
        "{%0,%1,%2,%3}, {%4,%5,%6,%7}, {%8,%9}, {%0,%1,%2,%3};\n"
        : "+f"(d[0]), "+f"(d[1]), "+f"(d[2]), "+f"(d[3])
        : "r"(a[0]), "r"(a[1]), "r"(a[2]), "r"(a[3]),
          "r"(b[0]), "r"(b[1]));
}

__device__ __forceinline__ void mma_f16(float* d, const uint32_t* a, const uint32_t* b)
{
    asm volatile(
        "mma.sync.aligned.m16n8k16.row.col.f32.f16.f16.f32 "
        "{%0,%1,%2,%3}, {%4,%5,%6,%7}, {%8,%9}, {%0,%1,%2,%3};\n"
        : "+f"(d[0]), "+f"(d[1]), "+f"(d[2]), "+f"(d[3])
        : "r"(a[0]), "r"(a[1]), "r"(a[2]), "r"(a[3]),
          "r"(b[0]), "r"(b[1]));
}

__device__ __forceinline__ void ldsm4(uint32_t* r, uint32_t saddr)
{
    asm volatile(
        "ldmatrix.sync.aligned.m8n8.x4.shared.b16 {%0,%1,%2,%3}, [%4];\n"
        : "=r"(r[0]), "=r"(r[1]), "=r"(r[2]), "=r"(r[3]) : "r"(saddr));
}

__device__ __forceinline__ uint32_t sptr(const void* p)
{
    return (uint32_t)__cvta_generic_to_shared(p);
}

__device__ __forceinline__ void cp16(uint32_t s, const void* g)
{
    asm volatile("cp.async.cg.shared.global [%0], [%1], 16;\n" :: "r"(s), "l"(g));
}

__device__ __forceinline__ uint32_t h2u(float a, float b)
{
    __half2 h = __floats2half2_rn(a, b);
    return *reinterpret_cast<uint32_t*>(&h);
}

// Combined elementwise tf32 rounding for x, Wq, Wk, Wo in one launch.
__global__ void round_all_kernel(
    const float* __restrict__ x,  const float* __restrict__ wq,
    const float* __restrict__ wk, const float* __restrict__ wo,
    float* __restrict__ xo, float* __restrict__ wqo,
    float* __restrict__ wko, float* __restrict__ woo)
{
    const int NX4 = MTOT * EDIM / 4;
    const int NW4 = EDIM * EDIM / 4;
    int i = blockIdx.x * blockDim.x + threadIdx.x;
    const float4* src; float4* dst; int j;
    if (i < NX4)                { src = (const float4*)x;  dst = (float4*)xo;  j = i; }
    else if (i < NX4 + NW4)     { src = (const float4*)wq; dst = (float4*)wqo; j = i - NX4; }
    else if (i < NX4 + 2 * NW4) { src = (const float4*)wk; dst = (float4*)wko; j = i - NX4 - NW4; }
    else if (i < NX4 + 3 * NW4) { src = (const float4*)wo; dst = (float4*)woo; j = i - NX4 - 2 * NW4; }
    else return;
    float4 v = src[j];
    float4 r;
    r.x = __uint_as_float(tf32_cvt(v.x));
    r.y = __uint_as_float(tf32_cvt(v.y));
    r.z = __uint_as_float(tf32_cvt(v.z));
    r.w = __uint_as_float(tf32_cvt(v.w));
    dst[j] = r;
}

// ---------------------------------------------------------------------------
// GEMM (NT), inputs pre-rounded tf32. cp.async 2-stage + LDSM fragments.
// (Known-good R8 version, 65us each.)
// ---------------------------------------------------------------------------
#define BM 128
#define BN 128
#define BK 32
#define SP 36
#define STG_FLOATS (2 * BM * SP)
#define GEMM_SMEM_BYTES (2 * STG_FLOATS * 4)

__device__ __forceinline__ void gemm_load_stage(
    float* stg, const float* A, const float* W,
    int m0, int n0, int k0, int K, int lr, int lc)
{
    float* as = stg;
    float* ws = stg + BM * SP;
#pragma unroll
    for (int i = 0; i < 4; i++) {
        cp16(sptr(&as[(lr + i * 32) * SP + lc]), &A[(size_t)(m0 + lr + i * 32) * K + k0 + lc]);
        cp16(sptr(&ws[(lr + i * 32) * SP + lc]), &W[(size_t)(n0 + lr + i * 32) * K + k0 + lc]);
    }
}

__global__ __launch_bounds__(256, 2) void gemm_tf32_bias(
    const float* __restrict__ A, const float* __restrict__ W,
    const float* __restrict__ bias, float* __restrict__ C,
    int M, int N, int K, int round_out)
{
    extern __shared__ float smg[];
    float* stg[2] = { smg, smg + STG_FLOATS };

    const int tid  = threadIdx.x;
    const int warp = tid >> 5;
    const int lane = tid & 31;
    const int g    = lane >> 2;
    const int t    = lane & 3;

    const int wm = (warp & 1) * 64;
    const int wn = (warp >> 1) * 32;
    const int m0 = blockIdx.y * BM;
    const int n0 = blockIdx.x * BN;

    const int lr = tid >> 3;
    const int lc = (tid & 7) * 4;

    uint32_t aab[4], bab[2];
    {
        const uint32_t base = sptr(smg);
        const int arow = ((lane >> 3) & 1) * 8 + (lane & 7);
        const int acol = ((lane >> 4) & 1) * 4;
#pragma unroll
        for (int mt = 0; mt < 4; mt++)
            aab[mt] = base + (uint32_t)(((wm + mt * 16 + arow) * SP + acol) * 4);
        const int brow = (lane >> 4) * 8 + (lane & 7);
        const int bcol = ((lane >> 3) & 1) * 4;
#pragma unroll
        for (int j = 0; j < 2; j++)
            bab[j] = base + (uint32_t)((BM * SP + (wn + j * 16 + brow) * SP + bcol) * 4);
    }
    const uint32_t stg_bytes = STG_FLOATS * 4;

    float acc[4][4][4];
#pragma unroll
    for (int i = 0; i < 4; i++)
#pragma unroll
        for (int j = 0; j < 4; j++)
#pragma unroll
            for (int c = 0; c < 4; c++) acc[i][j][c] = 0.0f;

    const int NIT = K / BK;

    gemm_load_stage(stg[0], A, W, m0, n0, 0, K, lr, lc);
    asm volatile("cp.async.commit_group;\n");

    for (int it = 0; it < NIT; it++) {
        asm volatile("cp.async.wait_group 0;\n");
        __syncthreads();

        if (it + 1 < NIT)
            gemm_load_stage(stg[(it + 1) & 1], A, W, m0, n0, (it + 1) * BK, K, lr, lc);
        asm volatile("cp.async.commit_group;\n");

        const uint32_t soff = (it & 1) * stg_bytes;

#pragma unroll
        for (int kc = 0; kc < 4; kc++) {
            const uint32_t koff = soff + kc * 32;
            uint32_t a[4][4], b[2][4];
#pragma unroll
            for (int mt = 0; mt < 4; mt++) ldsm4(a[mt], aab[mt] + koff);
#pragma unroll
            for (int j = 0; j < 2; j++)    ldsm4(b[j],  bab[j] + koff);
#pragma unroll
            for (int mt = 0; mt < 4; mt++)
#pragma unroll
                for (int j = 0; j < 2; j++) {
                    mma_tf32(acc[mt][2 * j    ], a[mt], &b[j][0]);
                    mma_tf32(acc[mt][2 * j + 1], a[mt], &b[j][2]);
                }
        }
    }

#pragma unroll
    for (int nt = 0; nt < 4; nt++) {
        const int n = n0 + wn + nt * 8 + 2 * t;
        const float2 bv = *reinterpret_cast<const float2*>(&bias[n]);
#pragma unroll
        for (int mt = 0; mt < 4; mt++) {
            const size_t r0 = (size_t)(m0 + wm + mt * 16 + g);
            const size_t r1 = r0 + 8;
            float v00 = acc[mt][nt][0] + bv.x, v01 = acc[mt][nt][1] + bv.y;
            float v10 = acc[mt][nt][2] + bv.x, v11 = acc[mt][nt][3] + bv.y;
            if (round_out) {
                v00 = __uint_as_float(tf32_cvt(v00));
                v01 = __uint_as_float(tf32_cvt(v01));
                v10 = __uint_as_float(tf32_cvt(v10));
                v11 = __uint_as_float(tf32_cvt(v11));
            }
            *reinterpret_cast<float2*>(&C[r0 * N + n]) = make_float2(v00, v01);
            *reinterpret_cast<float2*>(&C[r1 * N + n]) = make_float2(v10, v11);
        }
    }
}

// ---------------------------------------------------------------------------
// Flash attention via mma.sync f16 (m16n8k16) + LDSM. fp32 softmax/accum.
// One CTA per (128 queries, head, batch). 8 warps x 16 query rows. V == K.
// K in two fp16 layouts: Kh [key][d] (QK^T B-op), Kd [d][key] (PV B-op).
// ---------------------------------------------------------------------------
#define HPIT 72   // halves; row stride 144B -> word-phase 4r mod 32, conflict-free
#define ATTN_SMEM_BYTES ((2 * 128 * HPIT + 2 * 64 * HPIT) * 2)

__global__ __launch_bounds__(256, 2) void attn_mma(
    const float* __restrict__ Q, const float* __restrict__ K,
    float* __restrict__ O)
{
    extern __shared__ __half smh[];
    __half* Qh = smh;                  // [128][HPIT] fp16(Q*0.125), [q][d]
    __half* Ph = Qh + 128 * HPIT;      // [128][HPIT] fp16(P), [q][key]
    __half* Kh = Ph + 128 * HPIT;      // [64][HPIT]  fp16(K), [key][d]
    __half* Kd = Kh + 64 * HPIT;       // [64][HPIT]  fp16(K), [d][key]

    const int tid  = threadIdx.x;
    const int warp = tid >> 5;
    const int lane = tid & 31;
    const int g = lane >> 2, t = lane & 3;
    const int wq = warp * 16;

    const int qt = blockIdx.x, h = blockIdx.y, b = blockIdx.z;
    const int q0 = qt * 128;

    // Load Q tile, scale by 0.125, convert fp16, [q][d].
    {
        const int r  = tid >> 1;
        const int dc = (tid & 1) * 32;
        const float* src = &Q[((size_t)(b * SEQ + q0 + r)) * EDIM + h * HD + dc];
        __half* dst = &Qh[r * HPIT + dc];
#pragma unroll
        for (int c = 0; c < 4; c++) {
            float4 v0 = *reinterpret_cast<const float4*>(src + c * 8);
            float4 v1 = *reinterpret_cast<const float4*>(src + c * 8 + 4);
            uint4 pk;
            pk.x = h2u(v0.x * 0.125f, v0.y * 0.125f);
            pk.y = h2u(v0.z * 0.125f, v0.w * 0.125f);
            pk.z = h2u(v1.x * 0.125f, v1.y * 0.125f);
            pk.w = h2u(v1.z * 0.125f, v1.w * 0.125f);
            *reinterpret_cast<uint4*>(dst + c * 8) = pk;
        }
    }

    // LDSM lane address pattern (same for A and B here):
    // row = (l&7) + ((l>>3)&1)*8 ; col(halves) = (l>>4)*8
    const int frow = (lane & 7) + ((lane >> 3) & 1) * 8;
    const int fcol = (lane >> 4) * 8;
    const uint32_t qa_base = sptr(Qh) + (uint32_t)(((wq + frow) * HPIT + fcol) * 2);
    const uint32_t pa_base = sptr(Ph) + (uint32_t)(((wq + frow) * HPIT + fcol) * 2);
    uint32_t kb_base[4], vb_base[4];
#pragma unroll
    for (int j = 0; j < 4; j++) {
        kb_base[j] = sptr(Kh) + (uint32_t)(((j * 16 + frow) * HPIT + fcol) * 2);
        vb_base[j] = sptr(Kd) + (uint32_t)(((j * 16 + frow) * HPIT + fcol) * 2);
    }

    float o[8][4];
#pragma unroll
    for (int i = 0; i < 8; i++)
#pragma unroll
        for (int j = 0; j < 4; j++) o[i][j] = 0.0f;
    float m0 = -1e30f, m1 = -1e30f, l0 = 0.0f, l1 = 0.0f;

    const int kr = tid >> 2;        // 0..63 key row
    const int kd = (tid & 3) << 4;  // 0,16,32,48 d-chunk base
    const float* kbase = &K[((size_t)(b * SEQ)) * EDIM + h * HD + kd];

    // Preload tile 0 into registers.
    float4 kv[4];
#pragma unroll
    for (int c = 0; c < 4; c++)
        kv[c] = *reinterpret_cast<const float4*>(kbase + (size_t)kr * EDIM + c * 4);

    for (int kt = 0; kt < SEQ / 64; kt++) {
        __syncthreads();  // prev PV done reading Kh/Kd; Qh store visible (iter 0)
        {
            // fp16 convert once; natural [key][d] ...
            uint4 pk;
            pk.x = h2u(kv[0].x, kv[0].y); pk.y = h2u(kv[0].z, kv[0].w);
            pk.z = h2u(kv[1].x, kv[1].y); pk.w = h2u(kv[1].z, kv[1].w);
            *reinterpret_cast<uint4*>(&Kh[kr * HPIT + kd]) = pk;
            uint4 pk2;
            pk2.x = h2u(kv[2].x, kv[2].y); pk2.y = h2u(kv[2].z, kv[2].w);
            pk2.z = h2u(kv[3].x, kv[3].y); pk2.w = h2u(kv[3].z, kv[3].w);
            *reinterpret_cast<uint4*>(&Kh[kr * HPIT + kd + 8]) = pk2;
            // ... and transposed [d][key]
#pragma unroll
            for (int c = 0; c < 4; c++) {
                const int db = kd + c * 4;
                Kd[(db + 0) * HPIT + kr] = __float2half_rn(kv[c].x);
                Kd[(db + 1) * HPIT + kr] = __float2half_rn(kv[c].y);
                Kd[(db + 2) * HPIT + kr] = __float2half_rn(kv[c].z);
                Kd[(db + 3) * HPIT + kr] = __float2half_rn(kv[c].w);
            }
        }
        __syncthreads();

        // ---- S = (Q*scale) K^T : 4 k16-chunks over d ----
        float s[8][4];
#pragma unroll
        for (int i = 0; i < 8; i++)
#pragma unroll
            for (int j = 0; j < 4; j++) s[i][j] = 0.0f;

#pragma unroll
        for (int kc = 0; kc < 4; kc++) {
            const uint32_t koff = kc * 32;   // 16 halves
            uint32_t a[4], bb[4][4];
            ldsm4(a, qa_base + koff);
#pragma unroll
            for (int j = 0; j < 4; j++) ldsm4(bb[j], kb_base[j] + koff);
#pragma unroll
            for (int jj = 0; jj < 8; jj++) {
                uint32_t b2[2] = { bb[jj >> 1][jj & 1], bb[jj >> 1][2 + (jj & 1)] };
                mma_f16(s[jj], a, b2);
            }
        }

        // Prefetch next K tile; latency hides under softmax + PV.
        if (kt + 1 < SEQ / 64) {
            const float* krow = kbase + (size_t)((kt + 1) * 64 + kr) * EDIM;
#pragma unroll
            for (int c = 0; c < 4; c++)
                kv[c] = *reinterpret_cast<const float4*>(krow + c * 4);
        }

        // ---- online softmax (rows g, g+8; quad holds a row) ----
        float rmax0 = -1e30f, rmax1 = -1e30f;
#pragma unroll
        for (int nt = 0; nt < 8; nt++) {
            rmax0 = fmaxf(rmax0, fmaxf(s[nt][0], s[nt][1]));
            rmax1 = fmaxf(rmax1, fmaxf(s[nt][2], s[nt][3]));
        }
#pragma unroll
        for (int off = 1; off <= 2; off <<= 1) {
            rmax0 = fmaxf(rmax0, __shfl_xor_sync(0xffffffffu, rmax0, off));
            rmax1 = fmaxf(rmax1, __shfl_xor_sync(0xffffffffu, rmax1, off));
        }
        const float mn0 = fmaxf(m0, rmax0);
        const float mn1 = fmaxf(m1, rmax1);
        const float al0 = __expf(m0 - mn0);
        const float al1 = __expf(m1 - mn1);
        m0 = mn0; m1 = mn1;

        float sum0 = 0.0f, sum1 = 0.0f;
#pragma unroll
        for (int nt = 0; nt < 8; nt++) {
            s[nt][0] = __expf(s[nt][0] - mn0);
            s[nt][1] = __expf(s[nt][1] - mn0);
            s[nt][2] = __expf(s[nt][2] - mn1);
            s[nt][3] = __expf(s[nt][3] - mn1);
            sum0 += s[nt][0] + s[nt][1];
            sum1 += s[nt][2] + s[nt][3];
        }
#pragma unroll
        for (int off = 1; off <= 2; off <<= 1) {
            sum0 += __shfl_xor_sync(0xffffffffu, sum0, off);
            sum1 += __shfl_xor_sync(0xffffffffu, sum1, off);
        }
        l0 = l0 * al0 + sum0;
        l1 = l1 * al1 + sum1;
#pragma unroll
        for (int nd = 0; nd < 8; nd++) {
            o[nd][0] *= al0; o[nd][1] *= al0;
            o[nd][2] *= al1; o[nd][3] *= al1;
        }

        // ---- stage P (fp16) to smem [q][key], own warp's rows ----
#pragma unroll
        for (int nt = 0; nt < 8; nt++) {
            *reinterpret_cast<uint32_t*>(&Ph[(wq + g    ) * HPIT + nt * 8 + 2 * t]) =
                h2u(s[nt][0], s[nt][1]);
            *reinterpret_cast<uint32_t*>(&Ph[(wq + g + 8) * HPIT + nt * 8 + 2 * t]) =
                h2u(s[nt][2], s[nt][3]);
        }
        __syncwarp();

        // ---- O += P @ V (V = K tile; B-op from Kd [d][key]) : 4 k16-chunks ----
#pragma unroll
        for (int kc = 0; kc < 4; kc++) {
            const uint32_t koff = kc * 32;   // 16 keys
            uint32_t a[4], bb[4][4];
            ldsm4(a, pa_base + koff);
#pragma unroll
            for (int j = 0; j < 4; j++) ldsm4(bb[j], vb_base[j] + koff);
#pragma unroll
            for (int nd = 0; nd < 8; nd++) {
                uint32_t b2[2] = { bb[nd >> 1][nd & 1], bb[nd >> 1][2 + (nd & 1)] };
                mma_f16(o[nd], a, b2);
            }
        }
    }

    // ---- normalize, round to tf32 (feeds GEMM3), write [B,S,E] ----
    const float inv0 = 1.0f / l0;
    const float inv1 = 1.0f / l1;
    const size_t row0 = (size_t)(b * SEQ + q0 + wq + g) * EDIM + h * HD;
    const size_t row1 = row0 + (size_t)8 * EDIM;
#pragma unroll
    for (int nd = 0; nd < 8; nd++) {
        const int col = nd * 8 + 2 * t;
        *reinterpret_cast<uint2*>(&O[row0 + col]) =
            make_uint2(tf32_cvt(o[nd][0] * inv0), tf32_cvt(o[nd][1] * inv0));
        *reinterpret_cast<uint2*>(&O[row1 + col]) =
            make_uint2(tf32_cvt(o[nd][2] * inv1), tf32_cvt(o[nd][3] * inv1));
    }
}

// ---------------------------------------------------------------------------
extern "C" void kernel_launch(void* const* d_in, const int* in_sizes, int n_in,
                              void* d_out, int out_size)
{
    const float* x  = (const float*)d_in[0];
    const float* Wq = (const float*)d_in[1];
    const float* bq = (const float*)d_in[2];
    const float* Wk = (const float*)d_in[3];
    const float* bk = (const float*)d_in[4];
    const float* Wo = (const float*)d_in[5];
    const float* bo = (const float*)d_in[6];
    float* out = (float*)d_out;

    float *Qb, *Kb, *Ob, *Xb, *Wqb, *Wkb, *Wob;
    cudaGetSymbolAddress((void**)&Qb,  g_Q);
    cudaGetSymbolAddress((void**)&Kb,  g_K);
    cudaGetSymbolAddress((void**)&Ob,  g_O);
    cudaGetSymbolAddress((void**)&Xb,  g_X);
    cudaGetSymbolAddress((void**)&Wqb, g_Wq);
    cudaGetSymbolAddress((void**)&Wkb, g_Wk);
    cudaGetSymbolAddress((void**)&Wob, g_Wo);

    cudaFuncSetAttribute(gemm_tf32_bias,
                         cudaFuncAttributeMaxDynamicSharedMemorySize,
                         GEMM_SMEM_BYTES);
    cudaFuncSetAttribute(attn_mma,
                         cudaFuncAttributeMaxDynamicSharedMemorySize,
                         ATTN_SMEM_BYTES);

    // Pre-round all GEMM inputs to tf32 in ONE launch (idempotent).
    {
        const int total = MTOT * EDIM / 4 + 3 * (EDIM * EDIM / 4);
        round_all_kernel<<<(total + 255) / 256, 256>>>(x, Wq, Wk, Wo,
                                                       Xb, Wqb, Wkb, Wob);
    }

    dim3 gblk(256);
    dim3 ggrid(EDIM / BN, MTOT / BM);   // (6, 64)

    // Q and K projections (outputs rounded to tf32 for attention)
    gemm_tf32_bias<<<ggrid, gblk, GEMM_SMEM_BYTES>>>(Xb, Wqb, bq, Qb, MTOT, EDIM, EDIM, 1);
    gemm_tf32_bias<<<ggrid, gblk, GEMM_SMEM_BYTES>>>(Xb, Wkb, bk, Kb, MTOT, EDIM, EDIM, 1);

    // Attention (V aliases K per the reference)
    dim3 agrid(SEQ / 128, NH, BATCH);   // (8, 12, 8)
    attn_mma<<<agrid, 256, ATTN_SMEM_BYTES>>>(Qb, Kb, Ob);

    // Output projection (fp32 output)
    gemm_tf32_bias<<<ggrid, gblk, GEMM_SMEM_BYTES>>>(Ob, Wob, bo, out, MTOT, EDIM, EDIM, 0);
}

// round 11
// speedup vs baseline: 6.1004x; 1.3970x over previous
#include <cuda_runtime.h>
#include <cuda_fp16.h>
#include <cstddef>
#include <cstdint>

#define EDIM   768
#define BATCH  8
#define SEQ    1024
#define NH     12
#define HD     64
#define MTOT   (BATCH * SEQ)   // 8192

// Scratch (no cudaMalloc allowed) — fp16 dataflow.
__device__ __half g_Xh [(size_t)MTOT * EDIM];
__device__ __half g_Wqh[(size_t)EDIM * EDIM];
__device__ __half g_Wkh[(size_t)EDIM * EDIM];
__device__ __half g_Woh[(size_t)EDIM * EDIM];
__device__ __half g_Qh [(size_t)MTOT * EDIM];   // (x@Wq^T + bq) * 0.125, fp16
__device__ __half g_Kh [(size_t)MTOT * EDIM];   // x@Wk^T + bk, fp16
__device__ __half g_Oh [(size_t)MTOT * EDIM];   // attention output, fp16

// ---------------------------------------------------------------------------
// helpers
// ---------------------------------------------------------------------------
__device__ __forceinline__ void mma_f16(float* d, const uint32_t* a, const uint32_t* b)
{
    asm volatile(
        "mma.sync.aligned.m16n8k16.row.col.f32.f16.f16.f32 "
        "{%0,%1,%2,%3}, {%4,%5,%6,%7}, {%8,%9}, {%0,%1,%2,%3};\n"
        : "+f"(d[0]), "+f"(d[1]), "+f"(d[2]), "+f"(d[3])
        : "r"(a[0]), "r"(a[1]), "r"(a[2]), "r"(a[3]),
          "r"(b[0]), "r"(b[1]));
}

__device__ __forceinline__ void ldsm4(uint32_t* r, uint32_t saddr)
{
    asm volatile(
        "ldmatrix.sync.aligned.m8n8.x4.shared.b16 {%0,%1,%2,%3}, [%4];\n"
        : "=r"(r[0]), "=r"(r[1]), "=r"(r[2]), "=r"(r[3]) : "r"(saddr));
}

__device__ __forceinline__ void ldsm4t(uint32_t* r, uint32_t saddr)
{
    asm volatile(
        "ldmatrix.sync.aligned.m8n8.x4.trans.shared.b16 {%0,%1,%2,%3}, [%4];\n"
        : "=r"(r[0]), "=r"(r[1]), "=r"(r[2]), "=r"(r[3]) : "r"(saddr));
}

__device__ __forceinline__ uint32_t sptr(const void* p)
{
    return (uint32_t)__cvta_generic_to_shared(p);
}

__device__ __forceinline__ void cp16(uint32_t s, const void* g)
{
    asm volatile("cp.async.cg.shared.global [%0], [%1], 16;\n" :: "r"(s), "l"(g));
}

__device__ __forceinline__ uint32_t h2u(float a, float b)
{
    __half2 h = __floats2half2_rn(a, b);
    return *reinterpret_cast<uint32_t*>(&h);
}

// Convert x, Wq, Wk, Wo to fp16 in one launch (8 floats per thread).
__global__ void cvt_half_kernel(
    const float* __restrict__ x,  const float* __restrict__ wq,
    const float* __restrict__ wk, const float* __restrict__ wo,
    __half* __restrict__ xo, __half* __restrict__ wqo,
    __half* __restrict__ wko, __half* __restrict__ woo)
{
    const int NX8 = MTOT * EDIM / 8;
    const int NW8 = EDIM * EDIM / 8;
    int i = blockIdx.x * blockDim.x + threadIdx.x;
    const float4* src; uint4* dst; int j;
    if (i < NX8)                { src = (const float4*)x;  dst = (uint4*)xo;  j = i; }
    else if (i < NX8 + NW8)     { src = (const float4*)wq; dst = (uint4*)wqo; j = i - NX8; }
    else if (i < NX8 + 2 * NW8) { src = (const float4*)wk; dst = (uint4*)wko; j = i - NX8 - NW8; }
    else if (i < NX8 + 3 * NW8) { src = (const float4*)wo; dst = (uint4*)woo; j = i - NX8 - 2 * NW8; }
    else return;
    float4 v0 = src[2 * j], v1 = src[2 * j + 1];
    uint4 pk;
    pk.x = h2u(v0.x, v0.y); pk.y = h2u(v0.z, v0.w);
    pk.z = h2u(v1.x, v1.y); pk.w = h2u(v1.z, v1.w);
    dst[j] = pk;
}

// ---------------------------------------------------------------------------
// GEMM (NT) fp16 m16n8k16: C[m][n] = (sum_k A[m][k]*W[n][k] + bias[n]) * scale
// CTA 128x128, BK=32, 8 warps (2m x 4n), warp tile 64x32.
// cp.async 2-stage double buffer; LDSM fragments; fp32 accum.
// out_half: write __half (Q/K/O chain), else float (final output).
// ---------------------------------------------------------------------------
#define BM 128
#define BN 128
#define BKH 32
#define SPH 40   // halves; row stride 80B (16B-aligned), word-phase 20r mod 32 distinct
#define STGH (2 * 128 * SPH)
#define GEMM_SMEM_BYTES (2 * STGH * 2)

__device__ __forceinline__ void gemm_load_stage_h(
    uint32_t sa, uint32_t sw, const __half* A, const __half* W,
    int m0, int n0, int k0, int K, int tid)
{
    const int r  = tid >> 1;            // 0..127
    const int g0 = (tid & 1) * 2;       // 16B-group base 0 or 2
#pragma unroll
    for (int j = 0; j < 2; j++) {
        const int gg = g0 + j;          // 0..3, each = 8 halves
        const uint32_t soff = (uint32_t)((r * SPH + gg * 8) * 2);
        cp16(sa + soff, &A[(size_t)(m0 + r) * K + k0 + gg * 8]);
        cp16(sw + soff, &W[(size_t)(n0 + r) * K + k0 + gg * 8]);
    }
}

__global__ __launch_bounds__(256, 2) void gemm_f16_bias(
    const __half* __restrict__ A, const __half* __restrict__ W,
    const float* __restrict__ bias, void* __restrict__ Cout,
    int M, int N, int K, float scale, int out_half)
{
    extern __shared__ __half smh[];
    const uint32_t base = sptr(smh);

    const int tid  = threadIdx.x;
    const int warp = tid >> 5;
    const int lane = tid & 31;
    const int g    = lane >> 2;
    const int t    = lane & 3;

    const int wm = (warp & 1) * 64;
    const int wn = (warp >> 1) * 32;
    const int m0 = blockIdx.y * BM;
    const int n0 = blockIdx.x * BN;

    // LDSM per-lane byte addresses (stage 0).
    const int frow = (lane & 7) + ((lane >> 3) & 1) * 8;
    const int fcol = (lane >> 4) * 8;   // halves
    uint32_t aab[4], bab[2];
#pragma unroll
    for (int mt = 0; mt < 4; mt++)
        aab[mt] = base + (uint32_t)(((wm + mt * 16 + frow) * SPH + fcol) * 2);
#pragma unroll
    for (int j = 0; j < 2; j++)
        bab[j] = base + (uint32_t)((128 * SPH + (wn + j * 16 + frow) * SPH + fcol) * 2);
    const uint32_t stg_bytes = STGH * 2;

    float acc[4][4][4];
#pragma unroll
    for (int i = 0; i < 4; i++)
#pragma unroll
        for (int j = 0; j < 4; j++)
#pragma unroll
            for (int c = 0; c < 4; c++) acc[i][j][c] = 0.0f;

    const int NIT = K / BKH;   // 24

    gemm_load_stage_h(base, base + 128 * SPH * 2, A, W, m0, n0, 0, K, tid);
    asm volatile("cp.async.commit_group;\n");

    for (int it = 0; it < NIT; it++) {
        asm volatile("cp.async.wait_group 0;\n");
        __syncthreads();

        if (it + 1 < NIT) {
            const uint32_t so = ((it + 1) & 1) * stg_bytes;
            gemm_load_stage_h(base + so, base + so + 128 * SPH * 2,
                              A, W, m0, n0, (it + 1) * BKH, K, tid);
        }
        asm volatile("cp.async.commit_group;\n");

        const uint32_t soff = (it & 1) * stg_bytes;

#pragma unroll
        for (int kc = 0; kc < 2; kc++) {          // 2 chunks of k16
            const uint32_t koff = soff + kc * 32; // 16 halves
            uint32_t a[4][4], b[2][4];
#pragma unroll
            for (int mt = 0; mt < 4; mt++) ldsm4(a[mt], aab[mt] + koff);
#pragma unroll
            for (int j = 0; j < 2; j++)    ldsm4(b[j],  bab[j] + koff);
#pragma unroll
            for (int mt = 0; mt < 4; mt++)
#pragma unroll
                for (int nt = 0; nt < 4; nt++) {
                    uint32_t b2[2] = { b[nt >> 1][nt & 1], b[nt >> 1][2 + (nt & 1)] };
                    mma_f16(acc[mt][nt], a[mt], b2);
                }
        }
    }

    // Epilogue: c0=(g,2t) c1=(g,2t+1) c2=(g+8,2t) c3=(g+8,2t+1)
#pragma unroll
    for (int nt = 0; nt < 4; nt++) {
        const int n = n0 + wn + nt * 8 + 2 * t;
        const float2 bv = *reinterpret_cast<const float2*>(&bias[n]);
#pragma unroll
        for (int mt = 0; mt < 4; mt++) {
            const size_t r0 = (size_t)(m0 + wm + mt * 16 + g);
            const size_t r1 = r0 + 8;
            const float v00 = (acc[mt][nt][0] + bv.x) * scale;
            const float v01 = (acc[mt][nt][1] + bv.y) * scale;
            const float v10 = (acc[mt][nt][2] + bv.x) * scale;
            const float v11 = (acc[mt][nt][3] + bv.y) * scale;
            if (out_half) {
                __half* Ch = (__half*)Cout;
                *reinterpret_cast<uint32_t*>(&Ch[r0 * N + n]) = h2u(v00, v01);
                *reinterpret_cast<uint32_t*>(&Ch[r1 * N + n]) = h2u(v10, v11);
            } else {
                float* Cf = (float*)Cout;
                *reinterpret_cast<float2*>(&Cf[r0 * N + n]) = make_float2(v00, v01);
                *reinterpret_cast<float2*>(&Cf[r1 * N + n]) = make_float2(v10, v11);
            }
        }
    }
}

// ---------------------------------------------------------------------------
// Flash attention, all-fp16 operands (fp32 softmax/accum). V == K.
// One CTA per (128 queries, head, batch). 8 warps x 16 query rows.
// Q (pre-scaled) and K arrive fp16 -> cp.async staging, K double-buffered.
// PV B-operand via ldmatrix.trans on the natural [key][d] K tile (no Kd).
// ---------------------------------------------------------------------------
#define HPIT 72   // halves; row stride 144B, word-phase 4r mod 32 -> conflict-free
#define KBUF_BYTES (64 * HPIT * 2)
#define ATTN_SMEM_BYTES ((2 * 128 * HPIT + 2 * 64 * HPIT) * 2)

__global__ __launch_bounds__(256, 2) void attn_mma(
    const __half* __restrict__ Q, const __half* __restrict__ K,
    __half* __restrict__ O)
{
    extern __shared__ __half smh[];
    __half* Qh = smh;                  // [128][HPIT] fp16(Q*0.125), [q][d]
    __half* Ph = Qh + 128 * HPIT;      // [128][HPIT] fp16(P), [q][key]
    __half* K0 = Ph + 128 * HPIT;      // [64][HPIT]  K tile buf0, [key][d]
    // buf1 at K0 + 64*HPIT

    const int tid  = threadIdx.x;
    const int warp = tid >> 5;
    const int lane = tid & 31;
    const int g = lane >> 2, t = lane & 3;
    const int wq = warp * 16;

    const int qt = blockIdx.x, h = blockIdx.y, b = blockIdx.z;
    const int q0 = qt * 128;

    // ---- prologue: cp.async Q tile (128x64) + K tile 0 (64x64), one group ----
    {
        const int r  = tid >> 1;
        const int cb = (tid & 1) * 32;
        const __half* src = &Q[((size_t)(b * SEQ + q0 + r)) * EDIM + h * HD + cb];
        const uint32_t dst = sptr(&Qh[r * HPIT + cb]);
#pragma unroll
        for (int j = 0; j < 4; j++)
            cp16(dst + j * 16, src + j * 8);
    }
    const int kr = tid >> 2;            // 0..63
    const int kc0 = (tid & 3) * 16;     // half-col base
    const __half* kbase = &K[((size_t)(b * SEQ)) * EDIM + h * HD];
    {
        const __half* src = kbase + (size_t)kr * EDIM + kc0;
        const uint32_t dst = sptr(&K0[kr * HPIT + kc0]);
        cp16(dst,      src);
        cp16(dst + 16, src + 8);
    }
    asm volatile("cp.async.commit_group;\n");

    // ---- LDSM per-lane byte addresses ----
    const int frow = (lane & 7) + ((lane >> 3) & 1) * 8;
    const int fcol = (lane >> 4) * 8;
    const uint32_t qa_base = sptr(Qh) + (uint32_t)(((wq + frow) * HPIT + fcol) * 2);
    const uint32_t pa_base = sptr(Ph) + (uint32_t)(((wq + frow) * HPIT + fcol) * 2);
    uint32_t kb_base[4];
#pragma unroll
    for (int j = 0; j < 4; j++)
        kb_base[j] = sptr(K0) + (uint32_t)(((j * 16 + frow) * HPIT + fcol) * 2);
    // trans pattern for PV B-op: keyrow = (l&7)+((l>>4)&1)*8, dcol = ((l>>3)&1)*8
    const int trow = (lane & 7) + ((lane >> 4) & 1) * 8;
    const int tcol = ((lane >> 3) & 1) * 8;
    uint32_t vb_base[4];
#pragma unroll
    for (int j = 0; j < 4; j++)
        vb_base[j] = sptr(K0) + (uint32_t)((trow * HPIT + j * 16 + tcol) * 2);

    float o[8][4];
#pragma unroll
    for (int i = 0; i < 8; i++)
#pragma unroll
        for (int j = 0; j < 4; j++) o[i][j] = 0.0f;
    float m0 = -1e30f, m1 = -1e30f, l0 = 0.0f, l1 = 0.0f;

    for (int kt = 0; kt < SEQ / 64; kt++) {
        asm volatile("cp.async.wait_group 0;\n");
        __syncthreads();   // K[kt] staged; all warps done with the other buffer

        // Prefetch K[kt+1] into the other buffer (its readers finished last iter).
        if (kt + 1 < SEQ / 64) {
            const __half* src = kbase + (size_t)((kt + 1) * 64 + kr) * EDIM + kc0;
            const uint32_t dst = sptr(&K0[((kt + 1) & 1) * 64 * HPIT + kr * HPIT + kc0]);
            cp16(dst,      src);
            cp16(dst + 16, src + 8);
        }
        asm volatile("cp.async.commit_group;\n");

        const uint32_t kbo = (uint32_t)((kt & 1) * KBUF_BYTES);

        // ---- S = Q K^T : 4 k16-chunks over d ----
        float s[8][4];
#pragma unroll
        for (int i = 0; i < 8; i++)
#pragma unroll
            for (int j = 0; j < 4; j++) s[i][j] = 0.0f;

#pragma unroll
        for (int kc = 0; kc < 4; kc++) {
            const uint32_t koff = kc * 32;   // 16 halves
            uint32_t a[4], bb[4][4];
            ldsm4(a, qa_base + koff);
#pragma unroll
            for (int j = 0; j < 4; j++) ldsm4(bb[j], kb_base[j] + kbo + koff);
#pragma unroll
            for (int jj = 0; jj < 8; jj++) {
                uint32_t b2[2] = { bb[jj >> 1][jj & 1], bb[jj >> 1][2 + (jj & 1)] };
                mma_f16(s[jj], a, b2);
            }
        }

        // ---- online softmax (rows g, g+8; quad holds a row) ----
        float rmax0 = -1e30f, rmax1 = -1e30f;
#pragma unroll
        for (int nt = 0; nt < 8; nt++) {
            rmax0 = fmaxf(rmax0, fmaxf(s[nt][0], s[nt][1]));
            rmax1 = fmaxf(rmax1, fmaxf(s[nt][2], s[nt][3]));
        }
#pragma unroll
        for (int off = 1; off <= 2; off <<= 1) {
            rmax0 = fmaxf(rmax0, __shfl_xor_sync(0xffffffffu, rmax0, off));
            rmax1 = fmaxf(rmax1, __shfl_xor_sync(0xffffffffu, rmax1, off));
        }
        const float mn0 = fmaxf(m0, rmax0);
        const float mn1 = fmaxf(m1, rmax1);
        const float al0 = __expf(m0 - mn0);
        const float al1 = __expf(m1 - mn1);
        m0 = mn0; m1 = mn1;

        float sum0 = 0.0f, sum1 = 0.0f;
#pragma unroll
        for (int nt = 0; nt < 8; nt++) {
            s[nt][0] = __expf(s[nt][0] - mn0);
            s[nt][1] = __expf(s[nt][1] - mn0);
            s[nt][2] = __expf(s[nt][2] - mn1);
            s[nt][3] = __expf(s[nt][3] - mn1);
            sum0 += s[nt][0] + s[nt][1];
            sum1 += s[nt][2] + s[nt][3];
        }
#pragma unroll
        for (int off = 1; off <= 2; off <<= 1) {
            sum0 += __shfl_xor_sync(0xffffffffu, sum0, off);
            sum1 += __shfl_xor_sync(0xffffffffu, sum1, off);
        }
        l0 = l0 * al0 + sum0;
        l1 = l1 * al1 + sum1;
#pragma unroll
        for (int nd = 0; nd < 8; nd++) {
            o[nd][0] *= al0; o[nd][1] *= al0;
            o[nd][2] *= al1; o[nd][3] *= al1;
        }

        // ---- stage P (fp16) [q][key], own warp's rows only ----
#pragma unroll
        for (int nt = 0; nt < 8; nt++) {
            *reinterpret_cast<uint32_t*>(&Ph[(wq + g    ) * HPIT + nt * 8 + 2 * t]) =
                h2u(s[nt][0], s[nt][1]);
            *reinterpret_cast<uint32_t*>(&Ph[(wq + g + 8) * HPIT + nt * 8 + 2 * t]) =
                h2u(s[nt][2], s[nt][3]);
        }
        __syncwarp();

        // ---- O += P @ V (V = K tile; B-op = trans-LDSM of [key][d]) ----
#pragma unroll
        for (int kc = 0; kc < 4; kc++) {
            uint32_t a[4], bb[4][4];
            ldsm4(a, pa_base + kc * 32);                       // P keys 16kc..+15
            const uint32_t vko = kbo + (uint32_t)(kc * 16 * HPIT * 2);
#pragma unroll
            for (int j = 0; j < 4; j++) ldsm4t(bb[j], vb_base[j] + vko);
#pragma unroll
            for (int nd = 0; nd < 8; nd++) {
                uint32_t b2[2] = { bb[nd >> 1][nd & 1], bb[nd >> 1][2 + (nd & 1)] };
                mma_f16(o[nd], a, b2);
            }
        }
    }

    // ---- normalize, write fp16 O [B,S,E] ----
    const float inv0 = 1.0f / l0;
    const float inv1 = 1.0f / l1;
    const size_t row0 = (size_t)(b * SEQ + q0 + wq + g) * EDIM + h * HD;
    const size_t row1 = row0 + (size_t)8 * EDIM;
#pragma unroll
    for (int nd = 0; nd < 8; nd++) {
        const int col = nd * 8 + 2 * t;
        *reinterpret_cast<uint32_t*>(&O[row0 + col]) =
            h2u(o[nd][0] * inv0, o[nd][1] * inv0);
        *reinterpret_cast<uint32_t*>(&O[row1 + col]) =
            h2u(o[nd][2] * inv1, o[nd][3] * inv1);
    }
}

// ---------------------------------------------------------------------------
extern "C" void kernel_launch(void* const* d_in, const int* in_sizes, int n_in,
                              void* d_out, int out_size)
{
    const float* x  = (const float*)d_in[0];
    const float* Wq = (const float*)d_in[1];
    const float* bq = (const float*)d_in[2];
    const float* Wk = (const float*)d_in[3];
    const float* bk = (const float*)d_in[4];
    const float* Wo = (const float*)d_in[5];
    const float* bo = (const float*)d_in[6];
    float* out = (float*)d_out;

    __half *Xh, *Wqh, *Wkh, *Woh, *Qh, *Kh, *Oh;
    cudaGetSymbolAddress((void**)&Xh,  g_Xh);
    cudaGetSymbolAddress((void**)&Wqh, g_Wqh);
    cudaGetSymbolAddress((void**)&Wkh, g_Wkh);
    cudaGetSymbolAddress((void**)&Woh, g_Woh);
    cudaGetSymbolAddress((void**)&Qh,  g_Qh);
    cudaGetSymbolAddress((void**)&Kh,  g_Kh);
    cudaGetSymbolAddress((void**)&Oh,  g_Oh);

    cudaFuncSetAttribute(gemm_f16_bias,
                         cudaFuncAttributeMaxDynamicSharedMemorySize,
                         GEMM_SMEM_BYTES);
    cudaFuncSetAttribute(attn_mma,
                         cudaFuncAttributeMaxDynamicSharedMemorySize,
                         ATTN_SMEM_BYTES);

    // fp16-convert all GEMM inputs in one launch.
    {
        const int total = MTOT * EDIM / 8 + 3 * (EDIM * EDIM / 8);
        cvt_half_kernel<<<(total + 255) / 256, 256>>>(x, Wq, Wk, Wo,
                                                      Xh, Wqh, Wkh, Woh);
    }

    dim3 gblk(256);
    dim3 ggrid(EDIM / BN, MTOT / BM);   // (6, 64)

    // Q projection (scale 1/sqrt(64) folded in) and K projection, fp16 out.
    gemm_f16_bias<<<ggrid, gblk, GEMM_SMEM_BYTES>>>(
        Xh, Wqh, bq, (void*)Qh, MTOT, EDIM, EDIM, 0.125f, 1);
    gemm_f16_bias<<<ggrid, gblk, GEMM_SMEM_BYTES>>>(
        Xh, Wkh, bk, (void*)Kh, MTOT, EDIM, EDIM, 1.0f, 1);

    // Attention (V aliases K per the reference), fp16 out.
    dim3 agrid(SEQ / 128, NH, BATCH);   // (8, 12, 8)
    attn_mma<<<agrid, 256, ATTN_SMEM_BYTES>>>(Qh, Kh, Oh);

    // Output projection, fp32 out.
    gemm_f16_bias<<<ggrid, gblk, GEMM_SMEM_BYTES>>>(
        Oh, Woh, bo, (void*)out, MTOT, EDIM, EDIM, 1.0f, 0);
}